// round 5
// baseline (speedup 1.0000x reference)
#include <cuda_runtime.h>
#include <cuda_bf16.h>
#include <math.h>
#include <stdint.h>

#define N_NODES 20000
#define NPAD    20096            // 157 * 128
#define N_EDGES 320000
#define HDIM    256
#define S_STEPS 4

typedef __nv_bfloat16 bf16;

// ---------------- device-global scratch (module-load allocated) -------------
__device__ bf16  g_Yh [NPAD * 512];      // [hn | agg] hi
__device__ bf16  g_Yl [NPAD * 512];      // [hn | agg] lo
__device__ float g_AB [NPAD * 512];      // [A | B] per node (fp32)
__device__ float g_P  [NPAD * 256];      // segsum(silu(hidden))
__device__ bf16  g_Ph [NPAD * 256];
__device__ bf16  g_Pl [NPAD * 256];
__device__ float g_G  [NPAD * 256];      // P @ eW2
__device__ bf16  g_Th [NPAD * 512];      // silu(y@nW1+nb1) hi
__device__ bf16  g_Tl [NPAD * 512];
__device__ bf16  g_eah[(size_t)N_EDGES * 64];
__device__ bf16  g_eal[(size_t)N_EDGES * 64];
// transposed split weights, per step ([N,K] row-major)
__device__ bf16  g_W1h[4 * 512 * 256], g_W1l[4 * 512 * 256];
__device__ bf16  g_Wch[4 * 256 * 64],  g_Wcl[4 * 256 * 64];
__device__ bf16  g_W2h[4 * 256 * 256], g_W2l[4 * 256 * 256];
__device__ bf16  g_N1h[4 * 512 * 512], g_N1l[4 * 512 * 512];
__device__ bf16  g_N2h[4 * 256 * 512], g_N2l[4 * 256 * 512];
__device__ float g_deg[N_NODES];
__device__ int   g_src[N_EDGES];
__device__ int   g_dst[N_EDGES];
__device__ int   g_is64;

__device__ __forceinline__ float silu_f(float v) {
    return __fdividef(v, 1.0f + __expf(-v));
}

__device__ __forceinline__ uint32_t smem_u32(const void* p) {
    uint32_t a;
    asm("{ .reg .u64 t; cvta.to.shared.u64 t, %1; cvt.u32.u64 %0, t; }"
        : "=r"(a) : "l"(p));
    return a;
}

// ====================== small elementwise kernels ============================
__global__ void detect_idx_kernel(const long long* __restrict__ p) {
    __shared__ int bad;
    if (threadIdx.x == 0) bad = 0;
    __syncthreads();
    long long v = p[threadIdx.x];
    if (v < 0 || v >= N_NODES) bad = 1;
    __syncthreads();
    if (threadIdx.x == 0) g_is64 = bad ? 0 : 1;
}

__global__ void convert_idx_kernel(const void* __restrict__ ei) {
    int e = blockIdx.x * blockDim.x + threadIdx.x;
    if (e >= N_EDGES) return;
    int s, d;
    if (g_is64) {
        const long long* p = (const long long*)ei;
        s = (int)p[e]; d = (int)p[N_EDGES + e];
    } else {
        const int* p = (const int*)ei;
        s = p[e]; d = p[N_EDGES + e];
    }
    g_src[e] = s; g_dst[e] = d;
    atomicAdd(&g_deg[d], 1.0f);
}

__global__ void split_kernel(const float* __restrict__ in,
                             bf16* __restrict__ oh, bf16* __restrict__ ol, long n) {
    long i = (long)blockIdx.x * blockDim.x + threadIdx.x;
    if (i >= n) return;
    float v = in[i];
    bf16 h = __float2bfloat16(v);
    bf16 l = __float2bfloat16(v - __bfloat162float(h));
    oh[i] = h; ol[i] = l;
}

// transpose + split: W [K,N] fp32 row-major -> out [N,K] hi/lo bf16
__global__ void tsplit_kernel(const float* __restrict__ W, int K, int N,
                              bf16* __restrict__ oh, bf16* __restrict__ ol) {
    __shared__ float tile[32][33];
    int k0 = blockIdx.y * 32, n0 = blockIdx.x * 32;
    int tx = threadIdx.x, ty = threadIdx.y;    // 32 x 8
    #pragma unroll
    for (int i = 0; i < 32; i += 8) {
        int k = k0 + ty + i, n = n0 + tx;
        tile[ty + i][tx] = (k < K && n < N) ? W[(long)k * N + n] : 0.0f;
    }
    __syncthreads();
    #pragma unroll
    for (int i = 0; i < 32; i += 8) {
        int n = n0 + ty + i, k = k0 + tx;
        if (n < N && k < K) {
            float v = tile[tx][ty + i];
            bf16 h = __float2bfloat16(v);
            bf16 l = __float2bfloat16(v - __bfloat162float(h));
            oh[(long)n * K + k] = h;
            ol[(long)n * K + k] = l;
        }
    }
}

// ---------------- layer norm -> split bf16 output ----------------------------
__global__ void ln_kernel(const float* __restrict__ x, long ldx,
                          const float* __restrict__ gamma,
                          const float* __restrict__ beta,
                          const float* __restrict__ preBias,
                          const float* __restrict__ deg,
                          bf16* __restrict__ outH, bf16* __restrict__ outL,
                          long ldo, int colOff) {
    int n = blockIdx.x, t = threadIdx.x;
    float v = x[(long)n * ldx + t];
    if (deg) v = v / fmaxf(deg[n], 1.0f) + preBias[t];
    float s = v, s2 = v * v;
    #pragma unroll
    for (int o = 16; o; o >>= 1) {
        s  += __shfl_xor_sync(0xFFFFFFFFu, s,  o);
        s2 += __shfl_xor_sync(0xFFFFFFFFu, s2, o);
    }
    __shared__ float as[8], as2[8];
    int w = t >> 5, l = t & 31;
    if (l == 0) { as[w] = s; as2[w] = s2; }
    __syncthreads();
    float S = 0.f, S2 = 0.f;
    #pragma unroll
    for (int i = 0; i < 8; i++) { S += as[i]; S2 += as2[i]; }
    float mean = S * (1.0f / 256.0f);
    float var  = S2 * (1.0f / 256.0f) - mean * mean;
    float rstd = rsqrtf(var + 1e-5f);
    float r = (v - mean) * rstd * gamma[t] + beta[t];
    bf16 h = __float2bfloat16(r);
    bf16 lo = __float2bfloat16(r - __bfloat162float(h));
    long off = (long)n * ldo + colOff + t;
    outH[off] = h; outL[off] = lo;
}

// ====================== shared MMA macros ====================================
#define LDSM4(R, ADDR) \
    asm volatile("ldmatrix.sync.aligned.m8n8.x4.shared.b16 {%0,%1,%2,%3}, [%4];" \
                 : "=r"((R)[0]), "=r"((R)[1]), "=r"((R)[2]), "=r"((R)[3]) : "r"(ADDR))

#define MMA16816(C, A, B0, B1) \
    asm volatile("mma.sync.aligned.m16n8k16.row.col.f32.bf16.bf16.f32 " \
                 "{%0,%1,%2,%3}, {%4,%5,%6,%7}, {%8,%9}, {%0,%1,%2,%3};" \
                 : "+f"((C)[0]), "+f"((C)[1]), "+f"((C)[2]), "+f"((C)[3]) \
                 : "r"((A)[0]), "r"((A)[1]), "r"((A)[2]), "r"((A)[3]), \
                   "r"(B0), "r"(B1))

#define CP16(DST, SRC) \
    asm volatile("cp.async.cg.shared.global [%0], [%1], 16;" :: "r"(DST), "l"(SRC))

// ============== HMMA split-bf16 GEMM: Out = op(A@B^T + bias) =================
// BM=128, BN=256, BK=32, 256 threads (8 warps = 2Mx4N, warp tile 64x64).
// 3-term split: D = Ah Bh + Al Bh + Ah Bl.  K % 32 == 0, K >= 64.
// A rows must be readable up to 128-multiple (scratch padded & zeroed).
#define PITCH 80
#define OFF_AH 0
#define OFF_AL 10240
#define OFF_BH 20480
#define OFF_BL 40960
#define STAGE  61440
#define GEMM_SMEM (3 * STAGE)

__global__ void __launch_bounds__(256, 1)
mma_gemm(const bf16* __restrict__ Ah, const bf16* __restrict__ Al, long lda,
         const bf16* __restrict__ Bh, const bf16* __restrict__ Bl, long ldb,
         const float* __restrict__ bias,
         float* __restrict__ Out, bf16* __restrict__ OutH, bf16* __restrict__ OutL,
         long ldo, int M, int K, int act, int accum) {
    extern __shared__ char smem[];
    const uint32_t sb = smem_u32(smem);
    const int tid  = threadIdx.x;
    const int lane = tid & 31;
    const int wid  = tid >> 5;
    const long bm = (long)blockIdx.y * 128;
    const long bn = (long)blockIdx.x * 256;
    const int wm = (wid & 1) * 64;       // warp M offset
    const int wn = (wid >> 1) * 64;      // warp N offset

    float acc[4][8][4];
    #pragma unroll
    for (int i = 0; i < 4; i++)
        #pragma unroll
        for (int j = 0; j < 8; j++)
            #pragma unroll
            for (int q = 0; q < 4; q++) acc[i][j][q] = 0.0f;

    const int nk = K >> 5;
    const int row4 = tid >> 2;           // 0..63
    const int ch   = tid & 3;            // 16B chunk within 64B row

    #define ISSUE(kt) do {                                                     \
        const uint32_t st = sb + ((kt) % 3) * STAGE;                           \
        const long k0 = (long)(kt) << 5;                                       \
        _Pragma("unroll")                                                      \
        for (int i = 0; i < 2; i++) {                                          \
            const int row = i * 64 + row4;                                     \
            CP16(st + OFF_AH + row * PITCH + ch * 16,                          \
                 Ah + (bm + row) * lda + k0 + ch * 8);                         \
            CP16(st + OFF_AL + row * PITCH + ch * 16,                          \
                 Al + (bm + row) * lda + k0 + ch * 8);                         \
        }                                                                      \
        _Pragma("unroll")                                                      \
        for (int i = 0; i < 4; i++) {                                          \
            const int row = i * 64 + row4;                                     \
            CP16(st + OFF_BH + row * PITCH + ch * 16,                          \
                 Bh + (bn + row) * ldb + k0 + ch * 8);                         \
            CP16(st + OFF_BL + row * PITCH + ch * 16,                          \
                 Bl + (bn + row) * ldb + k0 + ch * 8);                         \
        }                                                                      \
        asm volatile("cp.async.commit_group;");                                \
    } while (0)

    ISSUE(0);
    ISSUE(1);

    const uint32_t a_off = (uint32_t)((wm + (lane & 15)) * PITCH + (lane >> 4) * 16);
    const uint32_t b_off = (uint32_t)((lane & 15) * PITCH + (lane >> 4) * 16);

    for (int kt = 0; kt < nk; kt++) {
        asm volatile("cp.async.wait_group 1;");
        __syncthreads();
        if (kt + 2 < nk) ISSUE(kt + 2);
        const uint32_t st = sb + (kt % 3) * STAGE;
        #pragma unroll
        for (int h = 0; h < 2; h++) {
            uint32_t ah[4][4], al[4][4];
            #pragma unroll
            for (int mi = 0; mi < 4; mi++) {
                LDSM4(ah[mi], st + OFF_AH + a_off + mi * (16 * PITCH) + h * 32);
                LDSM4(al[mi], st + OFF_AL + a_off + mi * (16 * PITCH) + h * 32);
            }
            #pragma unroll
            for (int jj = 0; jj < 4; jj++) {
                uint32_t bh[4], bl[4];
                LDSM4(bh, st + OFF_BH + b_off + (wn + jj * 16) * PITCH + h * 32);
                LDSM4(bl, st + OFF_BL + b_off + (wn + jj * 16) * PITCH + h * 32);
                #pragma unroll
                for (int mi = 0; mi < 4; mi++)
                    #pragma unroll
                    for (int jo = 0; jo < 2; jo++) {
                        const int j = jj * 2 + jo;
                        MMA16816(acc[mi][j], ah[mi], bh[jo], bh[2 + jo]);
                        MMA16816(acc[mi][j], al[mi], bh[jo], bh[2 + jo]);
                        MMA16816(acc[mi][j], ah[mi], bl[jo], bl[2 + jo]);
                    }
            }
        }
    }

    // ---------------- epilogue ----------------
    const int r0 = lane >> 2;
    const int c0 = (lane & 3) * 2;
    float2 bv[8];
    if (bias) {
        #pragma unroll
        for (int j = 0; j < 8; j++)
            bv[j] = *(const float2*)&bias[bn + wn + j * 8 + c0];
    } else {
        #pragma unroll
        for (int j = 0; j < 8; j++) bv[j] = make_float2(0.f, 0.f);
    }
    #pragma unroll
    for (int mi = 0; mi < 4; mi++) {
        #pragma unroll
        for (int half = 0; half < 2; half++) {
            const long m = bm + wm + mi * 16 + r0 + half * 8;
            if (m >= M) continue;
            #pragma unroll
            for (int j = 0; j < 8; j++) {
                float x = acc[mi][j][half * 2 + 0] + bv[j].x;
                float y = acc[mi][j][half * 2 + 1] + bv[j].y;
                if (act) { x = silu_f(x); y = silu_f(y); }
                const long col = bn + wn + j * 8 + c0;
                if (OutH) {
                    bf16 hx = __float2bfloat16(x), hy = __float2bfloat16(y);
                    bf16 lx = __float2bfloat16(x - __bfloat162float(hx));
                    bf16 ly = __float2bfloat16(y - __bfloat162float(hy));
                    uint32_t hw = ((uint32_t)__bfloat16_as_ushort(hy) << 16) |
                                  __bfloat16_as_ushort(hx);
                    uint32_t lw = ((uint32_t)__bfloat16_as_ushort(ly) << 16) |
                                  __bfloat16_as_ushort(lx);
                    *(uint32_t*)(OutH + m * ldo + col) = hw;
                    *(uint32_t*)(OutL + m * ldo + col) = lw;
                } else {
                    float* o = Out + m * ldo + col;
                    if (accum) {
                        float2 old = *(const float2*)o;
                        x += old.x; y += old.y;
                    }
                    *(float2*)o = make_float2(x, y);
                }
            }
        }
    }
    #undef ISSUE
}

// ====== fused edge kernel: P += silu(ea@W1c + eb1 + A[src] + B[dst]) =========
// One CTA per 128 edges. K=64, N=256. MMA in smem (pitch 144), C staged via
// smem (pitch 132 floats), gather + silu + red.v4 scatter into g_P.
#define EPITCH 144
#define EOFF_EH 0
#define EOFF_EL 18432
#define EOFF_WH 36864
#define EOFF_WL 73728
#define EOFF_IDX 110592
#define EDGE_SMEM (110592 + 1024)

__global__ void __launch_bounds__(256, 1)
edge_fused(const bf16* __restrict__ Wch_, const bf16* __restrict__ Wcl_,
           const float* __restrict__ eb1_) {
    extern __shared__ char smem[];
    const uint32_t sb = smem_u32(smem);
    const int tid = threadIdx.x, lane = tid & 31, wid = tid >> 5;
    const int bm = blockIdx.x * 128;
    const int wm = (wid & 1) * 64;
    const int wn = (wid >> 1) * 64;

    int* s_src = (int*)(smem + EOFF_IDX);
    int* s_dst = (int*)(smem + EOFF_IDX + 512);
    if (tid < 128) { s_src[tid] = g_src[bm + tid]; s_dst[tid] = g_dst[bm + tid]; }

    {
        const int row8 = tid >> 3, ch = tid & 7;
        #pragma unroll
        for (int i = 0; i < 4; i++) {
            const int row = i * 32 + row8;
            CP16(sb + EOFF_EH + row * EPITCH + ch * 16,
                 g_eah + (long)(bm + row) * 64 + ch * 8);
            CP16(sb + EOFF_EL + row * EPITCH + ch * 16,
                 g_eal + (long)(bm + row) * 64 + ch * 8);
        }
        #pragma unroll
        for (int i = 0; i < 8; i++) {
            const int row = i * 32 + row8;
            CP16(sb + EOFF_WH + row * EPITCH + ch * 16, Wch_ + (long)row * 64 + ch * 8);
            CP16(sb + EOFF_WL + row * EPITCH + ch * 16, Wcl_ + (long)row * 64 + ch * 8);
        }
        asm volatile("cp.async.commit_group;");
        asm volatile("cp.async.wait_group 0;");
    }
    __syncthreads();

    float acc[4][8][4];
    #pragma unroll
    for (int i = 0; i < 4; i++)
        #pragma unroll
        for (int j = 0; j < 8; j++)
            #pragma unroll
            for (int q = 0; q < 4; q++) acc[i][j][q] = 0.0f;

    const uint32_t a_off = (uint32_t)((wm + (lane & 15)) * EPITCH + (lane >> 4) * 16);
    const uint32_t b_off = (uint32_t)((lane & 15) * EPITCH + (lane >> 4) * 16);
    #pragma unroll
    for (int h = 0; h < 4; h++) {
        uint32_t ah[4][4], al[4][4];
        #pragma unroll
        for (int mi = 0; mi < 4; mi++) {
            LDSM4(ah[mi], sb + EOFF_EH + a_off + mi * (16 * EPITCH) + h * 32);
            LDSM4(al[mi], sb + EOFF_EL + a_off + mi * (16 * EPITCH) + h * 32);
        }
        #pragma unroll
        for (int jj = 0; jj < 4; jj++) {
            uint32_t bh[4], bl[4];
            LDSM4(bh, sb + EOFF_WH + b_off + (wn + jj * 16) * EPITCH + h * 32);
            LDSM4(bl, sb + EOFF_WL + b_off + (wn + jj * 16) * EPITCH + h * 32);
            #pragma unroll
            for (int mi = 0; mi < 4; mi++)
                #pragma unroll
                for (int jo = 0; jo < 2; jo++) {
                    const int j = jj * 2 + jo;
                    MMA16816(acc[mi][j], ah[mi], bh[jo], bh[2 + jo]);
                    MMA16816(acc[mi][j], al[mi], bh[jo], bh[2 + jo]);
                    MMA16816(acc[mi][j], ah[mi], bl[jo], bl[2 + jo]);
                }
        }
    }
    __syncthreads();

    // stage C through smem in two 128-col passes, gather + silu + scatter
    float* Cst = (float*)smem;
    const int r0 = lane >> 2;
    const int c0 = (lane & 3) * 2;
    #pragma unroll 1
    for (int nh = 0; nh < 2; nh++) {
        if ((wid >> 1) == 2 * nh || (wid >> 1) == 2 * nh + 1) {
            const int cb = wn - nh * 128;
            #pragma unroll
            for (int mi = 0; mi < 4; mi++)
                #pragma unroll
                for (int half = 0; half < 2; half++) {
                    const int row = wm + mi * 16 + r0 + half * 8;
                    #pragma unroll
                    for (int j = 0; j < 8; j++)
                        *(float2*)&Cst[row * 132 + cb + j * 8 + c0] =
                            make_float2(acc[mi][j][half * 2], acc[mi][j][half * 2 + 1]);
                }
        }
        __syncthreads();
        const float4 bias4 = *(const float4*)&eb1_[nh * 128 + lane * 4];
        #pragma unroll 1
        for (int rr = 0; rr < 16; rr++) {
            const int row = wid * 16 + rr;
            const int s = s_src[row];
            const int d = s_dst[row];
            float4 c4 = *(const float4*)&Cst[row * 132 + lane * 4];
            const float4 a4 = *(const float4*)&g_AB[(long)s * 512 + nh * 128 + lane * 4];
            const float4 b4 = *(const float4*)&g_AB[(long)d * 512 + 256 + nh * 128 + lane * 4];
            float v0 = silu_f(a4.x + b4.x + c4.x + bias4.x);
            float v1 = silu_f(a4.y + b4.y + c4.y + bias4.y);
            float v2 = silu_f(a4.z + b4.z + c4.z + bias4.z);
            float v3 = silu_f(a4.w + b4.w + c4.w + bias4.w);
            float* p = &g_P[(long)d * 256 + nh * 128 + lane * 4];
            asm volatile("red.global.add.v4.f32 [%0], {%1,%2,%3,%4};"
                         :: "l"(p), "f"(v0), "f"(v1), "f"(v2), "f"(v3) : "memory");
        }
        __syncthreads();
    }
}

// ============================ launch =========================================
extern "C" void kernel_launch(void* const* d_in, const int* in_sizes, int n_in,
                              void* d_out, int out_size) {
    const float* node_state = (const float*)d_in[0];
    const float* edge_attr  = (const float*)d_in[1];
    const float* nn_g = (const float*)d_in[2];
    const float* nn_b = (const float*)d_in[3];
    const float* mn_g = (const float*)d_in[4];
    const float* mn_b = (const float*)d_in[5];
    const float* eW1  = (const float*)d_in[6];
    const float* eb1  = (const float*)d_in[7];
    const float* eW2  = (const float*)d_in[8];
    const float* eb2  = (const float*)d_in[9];
    const float* nW1  = (const float*)d_in[10];
    const float* nb1  = (const float*)d_in[11];
    const float* nW2  = (const float*)d_in[12];
    const float* nb2  = (const float*)d_in[13];
    const void*  eidx = d_in[14];
    float* h = (float*)d_out;

    cudaFuncSetAttribute(mma_gemm, cudaFuncAttributeMaxDynamicSharedMemorySize,
                         GEMM_SMEM);
    cudaFuncSetAttribute(edge_fused, cudaFuncAttributeMaxDynamicSharedMemorySize,
                         EDGE_SMEM);

    void *pYh, *pYl, *pAB, *pP, *pPh, *pPl, *pG, *pTh, *pTl,
         *pEah, *pEal, *pW1h, *pW1l, *pWch, *pWcl, *pW2h, *pW2l,
         *pN1h, *pN1l, *pN2h, *pN2l, *pdeg;
    cudaGetSymbolAddress(&pYh, g_Yh);   cudaGetSymbolAddress(&pYl, g_Yl);
    cudaGetSymbolAddress(&pAB, g_AB);
    cudaGetSymbolAddress(&pP, g_P);     cudaGetSymbolAddress(&pPh, g_Ph);
    cudaGetSymbolAddress(&pPl, g_Pl);   cudaGetSymbolAddress(&pG, g_G);
    cudaGetSymbolAddress(&pTh, g_Th);   cudaGetSymbolAddress(&pTl, g_Tl);
    cudaGetSymbolAddress(&pEah, g_eah); cudaGetSymbolAddress(&pEal, g_eal);
    cudaGetSymbolAddress(&pW1h, g_W1h); cudaGetSymbolAddress(&pW1l, g_W1l);
    cudaGetSymbolAddress(&pWch, g_Wch); cudaGetSymbolAddress(&pWcl, g_Wcl);
    cudaGetSymbolAddress(&pW2h, g_W2h); cudaGetSymbolAddress(&pW2l, g_W2l);
    cudaGetSymbolAddress(&pN1h, g_N1h); cudaGetSymbolAddress(&pN1l, g_N1l);
    cudaGetSymbolAddress(&pN2h, g_N2h); cudaGetSymbolAddress(&pN2l, g_N2l);
    cudaGetSymbolAddress(&pdeg, g_deg);

    bf16 *Yh=(bf16*)pYh, *Yl=(bf16*)pYl, *Ph=(bf16*)pPh, *Pl=(bf16*)pPl,
         *Th=(bf16*)pTh, *Tl=(bf16*)pTl, *Eah=(bf16*)pEah, *Eal=(bf16*)pEal,
         *W1h=(bf16*)pW1h, *W1l=(bf16*)pW1l, *Wch=(bf16*)pWch, *Wcl=(bf16*)pWcl,
         *W2h=(bf16*)pW2h, *W2l=(bf16*)pW2l, *N1h=(bf16*)pN1h, *N1l=(bf16*)pN1l,
         *N2h=(bf16*)pN2h, *N2l=(bf16*)pN2l;
    float *AB=(float*)pAB, *P=(float*)pP, *G=(float*)pG, *deg=(float*)pdeg;

    // ---- one-time prep ----
    cudaMemcpyAsync(h, node_state, (size_t)N_NODES * HDIM * sizeof(float),
                    cudaMemcpyDeviceToDevice, 0);
    cudaMemsetAsync(pdeg, 0, N_NODES * sizeof(float), 0);
    detect_idx_kernel<<<1, 64>>>((const long long*)eidx);
    convert_idx_kernel<<<(N_EDGES + 255) / 256, 256>>>(eidx);
    split_kernel<<<((long)N_EDGES * 64 + 255) / 256, 256>>>(edge_attr, Eah, Eal,
                                                            (long)N_EDGES * 64);
    dim3 tb(32, 8);
    for (int i = 0; i < S_STEPS; i++) {
        const float* W1 = eW1 + (long)i * 576 * 256;
        tsplit_kernel<<<dim3(8, 8), tb>>>(W1, 256, 256,
                                          W1h + (long)i * 512 * 256,
                                          W1l + (long)i * 512 * 256);
        tsplit_kernel<<<dim3(8, 8), tb>>>(W1 + 256 * 256, 256, 256,
                                          W1h + (long)i * 512 * 256 + 256 * 256,
                                          W1l + (long)i * 512 * 256 + 256 * 256);
        tsplit_kernel<<<dim3(8, 2), tb>>>(W1 + 512 * 256, 64, 256,
                                          Wch + (long)i * 256 * 64,
                                          Wcl + (long)i * 256 * 64);
        tsplit_kernel<<<dim3(8, 8), tb>>>(eW2 + (long)i * 256 * 256, 256, 256,
                                          W2h + (long)i * 256 * 256,
                                          W2l + (long)i * 256 * 256);
        tsplit_kernel<<<dim3(16, 16), tb>>>(nW1 + (long)i * 512 * 512, 512, 512,
                                            N1h + (long)i * 512 * 512,
                                            N1l + (long)i * 512 * 512);
        tsplit_kernel<<<dim3(8, 16), tb>>>(nW2 + (long)i * 512 * 256, 512, 256,
                                           N2h + (long)i * 256 * 512,
                                           N2l + (long)i * 256 * 512);
    }

    const int MT = NPAD / 128;     // 157 M-tiles (node GEMMs)

    for (int i = 0; i < S_STEPS; i++) {
        // 1. hn = LN(h) -> Y[:, 0:256]
        ln_kernel<<<N_NODES, 256>>>(h, 256, nn_g + i * HDIM, nn_b + i * HDIM,
                                    nullptr, nullptr, Yh, Yl, 512, 0);
        // 2. AB = hn @ [W1a|W1b]   (M=20000, K=256, N=512)
        mma_gemm<<<dim3(2, MT), 256, GEMM_SMEM>>>(
            Yh, Yl, 512, W1h + (long)i * 512 * 256, W1l + (long)i * 512 * 256, 256,
            nullptr, AB, nullptr, nullptr, 512, N_NODES, 256, 0, 0);
        // 3+4. P = segsum_dst(silu(ea@W1c + eb1 + A[src] + B[dst]))
        cudaMemsetAsync(pP, 0, (size_t)N_NODES * 256 * sizeof(float), 0);
        edge_fused<<<N_EDGES / 128, 256, EDGE_SMEM>>>(
            Wch + (long)i * 256 * 64, Wcl + (long)i * 256 * 64, eb1 + i * HDIM);
        split_kernel<<<((long)N_NODES * 256 + 255) / 256, 256>>>(P, Ph, Pl,
                                                                 (long)N_NODES * 256);
        // 5. G = P @ eW2           (M=20000, K=256, N=256)
        mma_gemm<<<dim3(1, MT), 256, GEMM_SMEM>>>(
            Ph, Pl, 256, W2h + (long)i * 256 * 256, W2l + (long)i * 256 * 256, 256,
            nullptr, G, nullptr, nullptr, 256, N_NODES, 256, 0, 0);
        // 6. agg = LN(G/deg + eb2) -> Y[:, 256:512]
        ln_kernel<<<N_NODES, 256>>>(G, 256, mn_g + i * HDIM, mn_b + i * HDIM,
                                    eb2 + i * HDIM, deg, Yh, Yl, 512, 256);
        // 7. T = silu(y @ nW1 + nb1)  (M=20000, K=512, N=512, split bf16 out)
        mma_gemm<<<dim3(2, MT), 256, GEMM_SMEM>>>(
            Yh, Yl, 512, N1h + (long)i * 512 * 512, N1l + (long)i * 512 * 512, 512,
            nb1 + i * 512, nullptr, Th, Tl, 512, N_NODES, 512, 1, 0);
        // 8. h += T @ nW2 + nb2    (M=20000, K=512, N=256, fp32 accum)
        mma_gemm<<<dim3(1, MT), 256, GEMM_SMEM>>>(
            Th, Tl, 512, N2h + (long)i * 256 * 512, N2l + (long)i * 256 * 512, 512,
            nb2 + i * HDIM, h, nullptr, nullptr, 256, N_NODES, 512, 0, 1);
    }
}

// round 6
// speedup vs baseline: 1.4453x; 1.4453x over previous
#include <cuda_runtime.h>
#include <cuda_bf16.h>
#include <math.h>
#include <stdint.h>

#define N_NODES 20000
#define NPAD    20096            // 157 * 128
#define N_EDGES 320000
#define ECHUNK  32000            // edges per locality chunk (C chunk = 32MB)
#define HDIM    256
#define S_STEPS 4

typedef __nv_bfloat16 bf16;

// ---------------- device-global scratch (module-load allocated) -------------
__device__ bf16  g_Yh [NPAD * 512];      // [hn | agg] hi
__device__ bf16  g_Yl [NPAD * 512];      // [hn | agg] lo
__device__ float g_AB [NPAD * 512];      // [A | B] per node (fp32)
__device__ float g_C  [(size_t)N_EDGES * 256];  // ea@W1c + b1 per edge
__device__ float g_P  [NPAD * 256];      // segsum(silu(hidden))
__device__ bf16  g_Ph [NPAD * 256];
__device__ bf16  g_Pl [NPAD * 256];
__device__ float g_G  [NPAD * 256];      // P @ eW2
__device__ bf16  g_Th [NPAD * 512];      // silu(y@nW1+nb1) hi
__device__ bf16  g_Tl [NPAD * 512];
__device__ bf16  g_eah[(size_t)N_EDGES * 64];
__device__ bf16  g_eal[(size_t)N_EDGES * 64];
// transposed split weights, per step ([N,K] row-major)
__device__ bf16  g_W1h[4 * 512 * 256], g_W1l[4 * 512 * 256];
__device__ bf16  g_Wch[4 * 256 * 64],  g_Wcl[4 * 256 * 64];
__device__ bf16  g_W2h[4 * 256 * 256], g_W2l[4 * 256 * 256];
__device__ bf16  g_N1h[4 * 512 * 512], g_N1l[4 * 512 * 512];
__device__ bf16  g_N2h[4 * 256 * 512], g_N2l[4 * 256 * 512];
__device__ float g_deg[N_NODES];
__device__ int   g_src[N_EDGES];
__device__ int   g_dst[N_EDGES];
__device__ int   g_is64;

__device__ __forceinline__ float silu_f(float v) {
    return __fdividef(v, 1.0f + __expf(-v));
}

__device__ __forceinline__ uint32_t smem_u32(const void* p) {
    uint32_t a;
    asm("{ .reg .u64 t; cvta.to.shared.u64 t, %1; cvt.u32.u64 %0, t; }"
        : "=r"(a) : "l"(p));
    return a;
}

// ====================== small elementwise kernels ============================
__global__ void detect_idx_kernel(const long long* __restrict__ p) {
    __shared__ int bad;
    if (threadIdx.x == 0) bad = 0;
    __syncthreads();
    long long v = p[threadIdx.x];
    if (v < 0 || v >= N_NODES) bad = 1;
    __syncthreads();
    if (threadIdx.x == 0) g_is64 = bad ? 0 : 1;
}

__global__ void convert_idx_kernel(const void* __restrict__ ei) {
    int e = blockIdx.x * blockDim.x + threadIdx.x;
    if (e >= N_EDGES) return;
    int s, d;
    if (g_is64) {
        const long long* p = (const long long*)ei;
        s = (int)p[e]; d = (int)p[N_EDGES + e];
    } else {
        const int* p = (const int*)ei;
        s = p[e]; d = p[N_EDGES + e];
    }
    g_src[e] = s; g_dst[e] = d;
    atomicAdd(&g_deg[d], 1.0f);
}

__global__ void split_kernel(const float* __restrict__ in,
                             bf16* __restrict__ oh, bf16* __restrict__ ol, long n) {
    long i = (long)blockIdx.x * blockDim.x + threadIdx.x;
    if (i >= n) return;
    float v = in[i];
    bf16 h = __float2bfloat16(v);
    bf16 l = __float2bfloat16(v - __bfloat162float(h));
    oh[i] = h; ol[i] = l;
}

// transpose + split: W [K,N] fp32 row-major -> out [N,K] hi/lo bf16
__global__ void tsplit_kernel(const float* __restrict__ W, int K, int N,
                              bf16* __restrict__ oh, bf16* __restrict__ ol) {
    __shared__ float tile[32][33];
    int k0 = blockIdx.y * 32, n0 = blockIdx.x * 32;
    int tx = threadIdx.x, ty = threadIdx.y;    // 32 x 8
    #pragma unroll
    for (int i = 0; i < 32; i += 8) {
        int k = k0 + ty + i, n = n0 + tx;
        tile[ty + i][tx] = (k < K && n < N) ? W[(long)k * N + n] : 0.0f;
    }
    __syncthreads();
    #pragma unroll
    for (int i = 0; i < 32; i += 8) {
        int n = n0 + ty + i, k = k0 + tx;
        if (n < N && k < K) {
            float v = tile[tx][ty + i];
            bf16 h = __float2bfloat16(v);
            bf16 l = __float2bfloat16(v - __bfloat162float(h));
            oh[(long)n * K + k] = h;
            ol[(long)n * K + k] = l;
        }
    }
}

// ---------------- layer norm -> split bf16 output ----------------------------
__global__ void ln_kernel(const float* __restrict__ x, long ldx,
                          const float* __restrict__ gamma,
                          const float* __restrict__ beta,
                          const float* __restrict__ preBias,
                          const float* __restrict__ deg,
                          bf16* __restrict__ outH, bf16* __restrict__ outL,
                          long ldo, int colOff) {
    int n = blockIdx.x, t = threadIdx.x;
    float v = x[(long)n * ldx + t];
    if (deg) v = v / fmaxf(deg[n], 1.0f) + preBias[t];
    float s = v, s2 = v * v;
    #pragma unroll
    for (int o = 16; o; o >>= 1) {
        s  += __shfl_xor_sync(0xFFFFFFFFu, s,  o);
        s2 += __shfl_xor_sync(0xFFFFFFFFu, s2, o);
    }
    __shared__ float as[8], as2[8];
    int w = t >> 5, l = t & 31;
    if (l == 0) { as[w] = s; as2[w] = s2; }
    __syncthreads();
    float S = 0.f, S2 = 0.f;
    #pragma unroll
    for (int i = 0; i < 8; i++) { S += as[i]; S2 += as2[i]; }
    float mean = S * (1.0f / 256.0f);
    float var  = S2 * (1.0f / 256.0f) - mean * mean;
    float rstd = rsqrtf(var + 1e-5f);
    float r = (v - mean) * rstd * gamma[t] + beta[t];
    bf16 h = __float2bfloat16(r);
    bf16 lo = __float2bfloat16(r - __bfloat162float(h));
    long off = (long)n * ldo + colOff + t;
    outH[off] = h; outL[off] = lo;
}

// ============== HMMA split-bf16 GEMM: Out = op(A@B^T + bias) =================
// BM=128, BN=128, BK=32, 256 threads (8 warps = 2Mx4N, warp tile 64x32).
// 3-term split: D = Ah Bh + Al Bh + Ah Bl.  K % 32 == 0.
#define PITCH 80                 // bytes per 32-bf16 row (conflict-free ldmatrix)
#define S_AH 0
#define S_AL 10240
#define S_BH 20480
#define S_BL 30720
#define STAGE 40960
#define GEMM_SMEM (2 * STAGE)

#define LDSM4(R, ADDR) \
    asm volatile("ldmatrix.sync.aligned.m8n8.x4.shared.b16 {%0,%1,%2,%3}, [%4];" \
                 : "=r"((R)[0]), "=r"((R)[1]), "=r"((R)[2]), "=r"((R)[3]) : "r"(ADDR))

#define MMA16816(C, A, B0, B1) \
    asm volatile("mma.sync.aligned.m16n8k16.row.col.f32.bf16.bf16.f32 " \
                 "{%0,%1,%2,%3}, {%4,%5,%6,%7}, {%8,%9}, {%0,%1,%2,%3};" \
                 : "+f"((C)[0]), "+f"((C)[1]), "+f"((C)[2]), "+f"((C)[3]) \
                 : "r"((A)[0]), "r"((A)[1]), "r"((A)[2]), "r"((A)[3]), \
                   "r"(B0), "r"(B1))

#define CP16(DST, SRC) \
    asm volatile("cp.async.cg.shared.global [%0], [%1], 16;" :: "r"(DST), "l"(SRC))

__global__ void __launch_bounds__(256, 1)
mma_gemm(const bf16* __restrict__ Ah, const bf16* __restrict__ Al, long lda,
         const bf16* __restrict__ Bh, const bf16* __restrict__ Bl, long ldb,
         const float* __restrict__ bias,
         float* __restrict__ Out, bf16* __restrict__ OutH, bf16* __restrict__ OutL,
         long ldo, int M, int K, int act, int accum) {
    extern __shared__ char smem[];
    const uint32_t sb = smem_u32(smem);
    const int tid  = threadIdx.x;
    const int lane = tid & 31;
    const int wid  = tid >> 5;
    const long bm = (long)blockIdx.y * 128;
    const long bn = (long)blockIdx.x * 128;
    const int wm = (wid & 1) * 64;       // warp M offset
    const int wn = (wid >> 1) * 32;      // warp N offset

    float acc[4][4][4];
    #pragma unroll
    for (int i = 0; i < 4; i++)
        #pragma unroll
        for (int j = 0; j < 4; j++)
            #pragma unroll
            for (int q = 0; q < 4; q++) acc[i][j][q] = 0.0f;

    const int nk = K >> 5;

    const int lrow0 = tid >> 2;          // 0..63 (+64 for odd sub-iter)
    const int lkc   = tid & 3;           // 16B chunk within 32-bf16 row

    #define ISSUE(kt) do {                                                     \
        const uint32_t st = sb + ((kt) & 1) * STAGE;                           \
        const long k0 = (long)(kt) << 5;                                       \
        _Pragma("unroll")                                                      \
        for (int i = 0; i < 8; i++) {                                          \
            const int part = i >> 1;                                           \
            const int row = lrow0 + (i & 1) * 64;                              \
            const uint32_t d = st + part * 10240 + row * PITCH + lkc * 16;     \
            const bf16* g;                                                     \
            if (part == 0)      g = Ah + (bm + row) * lda + k0 + lkc * 8;      \
            else if (part == 1) g = Al + (bm + row) * lda + k0 + lkc * 8;      \
            else if (part == 2) g = Bh + (bn + row) * ldb + k0 + lkc * 8;      \
            else                g = Bl + (bn + row) * ldb + k0 + lkc * 8;      \
            CP16(d, g);                                                        \
        }                                                                      \
        asm volatile("cp.async.commit_group;");                                \
    } while (0)

    ISSUE(0);

    const uint32_t a_off = (uint32_t)((wm + (lane & 15)) * PITCH + (lane >> 4) * 16);
    const uint32_t b_off = (uint32_t)((wn + (lane & 15)) * PITCH + (lane >> 4) * 16);

    for (int kt = 0; kt < nk; kt++) {
        if (kt + 1 < nk) {
            ISSUE(kt + 1);
            asm volatile("cp.async.wait_group 1;");
        } else {
            asm volatile("cp.async.wait_group 0;");
        }
        __syncthreads();
        const uint32_t st = sb + (kt & 1) * STAGE;
        #pragma unroll
        for (int h = 0; h < 2; h++) {
            uint32_t ah[4][4], al[4][4];
            #pragma unroll
            for (int mi = 0; mi < 4; mi++) {
                LDSM4(ah[mi], st + S_AH + a_off + mi * (16 * PITCH) + h * 32);
                LDSM4(al[mi], st + S_AL + a_off + mi * (16 * PITCH) + h * 32);
            }
            uint32_t bh[2][4], bl[2][4];
            #pragma unroll
            for (int jj = 0; jj < 2; jj++) {
                LDSM4(bh[jj], st + S_BH + b_off + jj * (16 * PITCH) + h * 32);
                LDSM4(bl[jj], st + S_BL + b_off + jj * (16 * PITCH) + h * 32);
            }
            #pragma unroll
            for (int mi = 0; mi < 4; mi++)
                #pragma unroll
                for (int j = 0; j < 4; j++) {
                    const int jj = j >> 1, jo = j & 1;
                    MMA16816(acc[mi][j], ah[mi], bh[jj][jo], bh[jj][2 + jo]);
                    MMA16816(acc[mi][j], al[mi], bh[jj][jo], bh[jj][2 + jo]);
                    MMA16816(acc[mi][j], ah[mi], bl[jj][jo], bl[jj][2 + jo]);
                }
        }
        __syncthreads();
    }

    // ---------------- epilogue ----------------
    const int r0 = lane >> 2;            // 0..7
    const int c0 = (lane & 3) * 2;       // 0,2,4,6
    float2 bv[4];
    if (bias) {
        #pragma unroll
        for (int j = 0; j < 4; j++)
            bv[j] = *(const float2*)&bias[bn + wn + j * 8 + c0];
    } else {
        #pragma unroll
        for (int j = 0; j < 4; j++) bv[j] = make_float2(0.f, 0.f);
    }
    #pragma unroll
    for (int mi = 0; mi < 4; mi++) {
        #pragma unroll
        for (int half = 0; half < 2; half++) {
            const long m = bm + wm + mi * 16 + r0 + half * 8;
            if (m >= M) continue;
            #pragma unroll
            for (int j = 0; j < 4; j++) {
                float x = acc[mi][j][half * 2 + 0] + bv[j].x;
                float y = acc[mi][j][half * 2 + 1] + bv[j].y;
                if (act) { x = silu_f(x); y = silu_f(y); }
                const long col = bn + wn + j * 8 + c0;
                if (OutH) {
                    bf16 hx = __float2bfloat16(x), hy = __float2bfloat16(y);
                    bf16 lx = __float2bfloat16(x - __bfloat162float(hx));
                    bf16 ly = __float2bfloat16(y - __bfloat162float(hy));
                    uint32_t hw = ((uint32_t)__bfloat16_as_ushort(hy) << 16) |
                                  __bfloat16_as_ushort(hx);
                    uint32_t lw = ((uint32_t)__bfloat16_as_ushort(ly) << 16) |
                                  __bfloat16_as_ushort(lx);
                    *(uint32_t*)(OutH + m * ldo + col) = hw;
                    *(uint32_t*)(OutL + m * ldo + col) = lw;
                } else {
                    float* o = Out + m * ldo + col;
                    if (accum) {
                        float2 old = *(const float2*)o;
                        x += old.x; y += old.y;
                    }
                    *(float2*)o = make_float2(x, y);
                }
            }
        }
    }
    #undef ISSUE
}

// ---------------- edge combine: silu(A[src]+B[dst]+C[e]) scatter into P -----
// processes ECHUNK edges starting at ebase (C row index == global edge index)
__global__ void edge_combine_kernel(int ebase) {
    long idx = (long)blockIdx.x * blockDim.x + threadIdx.x;  // ECHUNK * 64 items
    int e = ebase + (int)(idx >> 6);
    int j = ((int)idx & 63) << 2;
    int s = g_src[e];
    int d = g_dst[e];
    float4 a = *(const float4*)&g_AB[(long)s * 512 + j];
    float4 b = *(const float4*)&g_AB[(long)d * 512 + 256 + j];
    float4 c = *(const float4*)&g_C[(long)e * 256 + j];
    float r0 = silu_f(a.x + b.x + c.x);
    float r1 = silu_f(a.y + b.y + c.y);
    float r2 = silu_f(a.z + b.z + c.z);
    float r3 = silu_f(a.w + b.w + c.w);
    float* p = &g_P[(long)d * 256 + j];
    asm volatile("red.global.add.v4.f32 [%0], {%1,%2,%3,%4};"
                 :: "l"(p), "f"(r0), "f"(r1), "f"(r2), "f"(r3) : "memory");
}

// ============================ launch =========================================
extern "C" void kernel_launch(void* const* d_in, const int* in_sizes, int n_in,
                              void* d_out, int out_size) {
    const float* node_state = (const float*)d_in[0];
    const float* edge_attr  = (const float*)d_in[1];
    const float* nn_g = (const float*)d_in[2];
    const float* nn_b = (const float*)d_in[3];
    const float* mn_g = (const float*)d_in[4];
    const float* mn_b = (const float*)d_in[5];
    const float* eW1  = (const float*)d_in[6];
    const float* eb1  = (const float*)d_in[7];
    const float* eW2  = (const float*)d_in[8];
    const float* eb2  = (const float*)d_in[9];
    const float* nW1  = (const float*)d_in[10];
    const float* nb1  = (const float*)d_in[11];
    const float* nW2  = (const float*)d_in[12];
    const float* nb2  = (const float*)d_in[13];
    const void*  eidx = d_in[14];
    float* h = (float*)d_out;

    cudaFuncSetAttribute(mma_gemm, cudaFuncAttributeMaxDynamicSharedMemorySize,
                         GEMM_SMEM);

    void *pYh, *pYl, *pAB, *pC, *pP, *pPh, *pPl, *pG, *pTh, *pTl,
         *pEah, *pEal, *pW1h, *pW1l, *pWch, *pWcl, *pW2h, *pW2l,
         *pN1h, *pN1l, *pN2h, *pN2l, *pdeg;
    cudaGetSymbolAddress(&pYh, g_Yh);   cudaGetSymbolAddress(&pYl, g_Yl);
    cudaGetSymbolAddress(&pAB, g_AB);   cudaGetSymbolAddress(&pC, g_C);
    cudaGetSymbolAddress(&pP, g_P);     cudaGetSymbolAddress(&pPh, g_Ph);
    cudaGetSymbolAddress(&pPl, g_Pl);   cudaGetSymbolAddress(&pG, g_G);
    cudaGetSymbolAddress(&pTh, g_Th);   cudaGetSymbolAddress(&pTl, g_Tl);
    cudaGetSymbolAddress(&pEah, g_eah); cudaGetSymbolAddress(&pEal, g_eal);
    cudaGetSymbolAddress(&pW1h, g_W1h); cudaGetSymbolAddress(&pW1l, g_W1l);
    cudaGetSymbolAddress(&pWch, g_Wch); cudaGetSymbolAddress(&pWcl, g_Wcl);
    cudaGetSymbolAddress(&pW2h, g_W2h); cudaGetSymbolAddress(&pW2l, g_W2l);
    cudaGetSymbolAddress(&pN1h, g_N1h); cudaGetSymbolAddress(&pN1l, g_N1l);
    cudaGetSymbolAddress(&pN2h, g_N2h); cudaGetSymbolAddress(&pN2l, g_N2l);
    cudaGetSymbolAddress(&pdeg, g_deg);

    bf16 *Yh=(bf16*)pYh, *Yl=(bf16*)pYl, *Ph=(bf16*)pPh, *Pl=(bf16*)pPl,
         *Th=(bf16*)pTh, *Tl=(bf16*)pTl, *Eah=(bf16*)pEah, *Eal=(bf16*)pEal,
         *W1h=(bf16*)pW1h, *W1l=(bf16*)pW1l, *Wch=(bf16*)pWch, *Wcl=(bf16*)pWcl,
         *W2h=(bf16*)pW2h, *W2l=(bf16*)pW2l, *N1h=(bf16*)pN1h, *N1l=(bf16*)pN1l,
         *N2h=(bf16*)pN2h, *N2l=(bf16*)pN2l;
    float *AB=(float*)pAB, *C=(float*)pC, *P=(float*)pP, *G=(float*)pG,
          *deg=(float*)pdeg;

    // ---- one-time prep ----
    cudaMemcpyAsync(h, node_state, (size_t)N_NODES * HDIM * sizeof(float),
                    cudaMemcpyDeviceToDevice, 0);
    cudaMemsetAsync(pdeg, 0, N_NODES * sizeof(float), 0);
    detect_idx_kernel<<<1, 64>>>((const long long*)eidx);
    convert_idx_kernel<<<(N_EDGES + 255) / 256, 256>>>(eidx);
    split_kernel<<<((long)N_EDGES * 64 + 255) / 256, 256>>>(edge_attr, Eah, Eal,
                                                            (long)N_EDGES * 64);
    dim3 tb(32, 8);
    for (int i = 0; i < S_STEPS; i++) {
        const float* W1 = eW1 + (long)i * 576 * 256;
        tsplit_kernel<<<dim3(8, 8), tb>>>(W1, 256, 256,
                                          W1h + (long)i * 512 * 256,
                                          W1l + (long)i * 512 * 256);
        tsplit_kernel<<<dim3(8, 8), tb>>>(W1 + 256 * 256, 256, 256,
                                          W1h + (long)i * 512 * 256 + 256 * 256,
                                          W1l + (long)i * 512 * 256 + 256 * 256);
        tsplit_kernel<<<dim3(8, 2), tb>>>(W1 + 512 * 256, 64, 256,
                                          Wch + (long)i * 256 * 64,
                                          Wcl + (long)i * 256 * 64);
        tsplit_kernel<<<dim3(8, 8), tb>>>(eW2 + (long)i * 256 * 256, 256, 256,
                                          W2h + (long)i * 256 * 256,
                                          W2l + (long)i * 256 * 256);
        tsplit_kernel<<<dim3(16, 16), tb>>>(nW1 + (long)i * 512 * 512, 512, 512,
                                            N1h + (long)i * 512 * 512,
                                            N1l + (long)i * 512 * 512);
        tsplit_kernel<<<dim3(8, 16), tb>>>(nW2 + (long)i * 512 * 256, 512, 256,
                                           N2h + (long)i * 256 * 512,
                                           N2l + (long)i * 256 * 512);
    }

    const int MT = NPAD / 128;         // 157 M-tiles (node GEMMs)
    const int CT = ECHUNK / 128;       // 250 M-tiles per edge chunk

    for (int i = 0; i < S_STEPS; i++) {
        // 1. hn = LN(h) -> Y[:, 0:256]
        ln_kernel<<<N_NODES, 256>>>(h, 256, nn_g + i * HDIM, nn_b + i * HDIM,
                                    nullptr, nullptr, Yh, Yl, 512, 0);
        // 2. AB = hn @ [W1a|W1b]   (M=20000, K=256, N=512)
        mma_gemm<<<dim3(4, MT), 256, GEMM_SMEM>>>(
            Yh, Yl, 512, W1h + (long)i * 512 * 256, W1l + (long)i * 512 * 256, 256,
            nullptr, AB, nullptr, nullptr, 512, N_NODES, 256, 0, 0);
        // 3+4 interleaved in L2-sized chunks:
        //   C[chunk] = ea[chunk] @ W1c + eb1;  P += silu(A[src]+B[dst]+C[chunk])
        cudaMemsetAsync(pP, 0, (size_t)N_NODES * 256 * sizeof(float), 0);
        for (int cb = 0; cb < N_EDGES; cb += ECHUNK) {
            mma_gemm<<<dim3(2, CT), 256, GEMM_SMEM>>>(
                Eah + (size_t)cb * 64, Eal + (size_t)cb * 64, 64,
                Wch + (long)i * 256 * 64, Wcl + (long)i * 256 * 64, 64,
                eb1 + i * HDIM, C + (size_t)cb * 256, nullptr, nullptr, 256,
                ECHUNK, 64, 0, 0);
            edge_combine_kernel<<<((long)ECHUNK * 64) / 256, 256>>>(cb);
        }
        split_kernel<<<((long)N_NODES * 256 + 255) / 256, 256>>>(P, Ph, Pl,
                                                                 (long)N_NODES * 256);
        // 5. G = P @ eW2           (M=20000, K=256, N=256)
        mma_gemm<<<dim3(2, MT), 256, GEMM_SMEM>>>(
            Ph, Pl, 256, W2h + (long)i * 256 * 256, W2l + (long)i * 256 * 256, 256,
            nullptr, G, nullptr, nullptr, 256, N_NODES, 256, 0, 0);
        // 6. agg = LN(G/deg + eb2) -> Y[:, 256:512]
        ln_kernel<<<N_NODES, 256>>>(G, 256, mn_g + i * HDIM, mn_b + i * HDIM,
                                    eb2 + i * HDIM, deg, Yh, Yl, 512, 256);
        // 7. T = silu(y @ nW1 + nb1)  (M=20000, K=512, N=512, split bf16 out)
        mma_gemm<<<dim3(4, MT), 256, GEMM_SMEM>>>(
            Yh, Yl, 512, N1h + (long)i * 512 * 512, N1l + (long)i * 512 * 512, 512,
            nb1 + i * 512, nullptr, Th, Tl, 512, N_NODES, 512, 1, 0);
        // 8. h += T @ nW2 + nb2    (M=20000, K=512, N=256, fp32 accum)
        mma_gemm<<<dim3(2, MT), 256, GEMM_SMEM>>>(
            Th, Tl, 512, N2h + (long)i * 256 * 512, N2l + (long)i * 256 * 512, 512,
            nb2 + i * HDIM, h, nullptr, nullptr, 256, N_NODES, 512, 0, 1);
    }
}

// round 7
// speedup vs baseline: 1.6084x; 1.1128x over previous
#include <cuda_runtime.h>
#include <cuda_bf16.h>
#include <math.h>
#include <stdint.h>

#define N_NODES 20000
#define NPAD    20096            // 157 * 128
#define N_EDGES 320000
#define HDIM    256
#define S_STEPS 4

typedef __nv_bfloat16 bf16;

// ---------------- device-global scratch (module-load allocated) -------------
__device__ bf16  g_Yh [NPAD * 512];      // [hn | agg] hi
__device__ bf16  g_Yl [NPAD * 512];      // [hn | agg] lo
__device__ float g_AB [NPAD * 512];      // [A | B] per node (fp32)
__device__ float g_C  [(size_t)N_EDGES * 256];  // ea@W1c + b1 per edge
__device__ float g_P  [NPAD * 256];      // segsum(silu(hidden))
__device__ bf16  g_Ph [NPAD * 256];
__device__ bf16  g_Pl [NPAD * 256];
__device__ float g_G  [NPAD * 256];      // P @ eW2
__device__ bf16  g_Th [NPAD * 512];      // silu(y@nW1+nb1) hi
__device__ bf16  g_Tl [NPAD * 512];
__device__ bf16  g_eah[(size_t)N_EDGES * 64];
__device__ bf16  g_eal[(size_t)N_EDGES * 64];
// transposed split weights, per step ([N,K] row-major)
__device__ bf16  g_W1h[4 * 512 * 256], g_W1l[4 * 512 * 256];
__device__ bf16  g_Wch[4 * 256 * 64],  g_Wcl[4 * 256 * 64];
__device__ bf16  g_W2h[4 * 256 * 256], g_W2l[4 * 256 * 256];
__device__ bf16  g_N1h[4 * 512 * 512], g_N1l[4 * 512 * 512];
__device__ bf16  g_N2h[4 * 256 * 512], g_N2l[4 * 256 * 512];
__device__ float g_deg[N_NODES];
__device__ int   g_src[N_EDGES];
__device__ int   g_dst[N_EDGES];
__device__ int   g_is64;

__device__ __forceinline__ float silu_f(float v) {
    return __fdividef(v, 1.0f + __expf(-v));
}

__device__ __forceinline__ uint32_t smem_u32(const void* p) {
    uint32_t a;
    asm("{ .reg .u64 t; cvta.to.shared.u64 t, %1; cvt.u32.u64 %0, t; }"
        : "=r"(a) : "l"(p));
    return a;
}

// ====================== small elementwise kernels ============================
__global__ void detect_idx_kernel(const long long* __restrict__ p) {
    __shared__ int bad;
    if (threadIdx.x == 0) bad = 0;
    __syncthreads();
    long long v = p[threadIdx.x];
    if (v < 0 || v >= N_NODES) bad = 1;
    __syncthreads();
    if (threadIdx.x == 0) g_is64 = bad ? 0 : 1;
}

__global__ void convert_idx_kernel(const void* __restrict__ ei) {
    int e = blockIdx.x * blockDim.x + threadIdx.x;
    if (e >= N_EDGES) return;
    int s, d;
    if (g_is64) {
        const long long* p = (const long long*)ei;
        s = (int)p[e]; d = (int)p[N_EDGES + e];
    } else {
        const int* p = (const int*)ei;
        s = p[e]; d = p[N_EDGES + e];
    }
    g_src[e] = s; g_dst[e] = d;
    atomicAdd(&g_deg[d], 1.0f);
}

__global__ void split_kernel(const float* __restrict__ in,
                             bf16* __restrict__ oh, bf16* __restrict__ ol, long n) {
    long i = (long)blockIdx.x * blockDim.x + threadIdx.x;
    if (i >= n) return;
    float v = in[i];
    bf16 h = __float2bfloat16(v);
    bf16 l = __float2bfloat16(v - __bfloat162float(h));
    oh[i] = h; ol[i] = l;
}

// one launch transposes+splits ALL per-step weights.
// blockIdx.z -> (step, matrix); oversized xy-grid with early exit.
__global__ void tsplit_all(const float* __restrict__ eW1,
                           const float* __restrict__ eW2,
                           const float* __restrict__ nW1,
                           const float* __restrict__ nW2) {
    const int z = blockIdx.z;
    const int step = z / 6, mat = z % 6;
    const float* W; int K, N; bf16 *oh, *ol;
    switch (mat) {
    case 0: W = eW1 + (long)step * 576 * 256;             K = 256; N = 256;
            oh = g_W1h + (long)step * 512 * 256;           ol = g_W1l + (long)step * 512 * 256;           break;
    case 1: W = eW1 + (long)step * 576 * 256 + 256 * 256; K = 256; N = 256;
            oh = g_W1h + (long)step * 512 * 256 + 256*256; ol = g_W1l + (long)step * 512 * 256 + 256*256; break;
    case 2: W = eW1 + (long)step * 576 * 256 + 512 * 256; K = 64;  N = 256;
            oh = g_Wch + (long)step * 256 * 64;            ol = g_Wcl + (long)step * 256 * 64;            break;
    case 3: W = eW2 + (long)step * 256 * 256;             K = 256; N = 256;
            oh = g_W2h + (long)step * 256 * 256;           ol = g_W2l + (long)step * 256 * 256;           break;
    case 4: W = nW1 + (long)step * 512 * 512;             K = 512; N = 512;
            oh = g_N1h + (long)step * 512 * 512;           ol = g_N1l + (long)step * 512 * 512;           break;
    default:W = nW2 + (long)step * 512 * 256;             K = 512; N = 256;
            oh = g_N2h + (long)step * 256 * 512;           ol = g_N2l + (long)step * 256 * 512;           break;
    }
    const int k0 = blockIdx.y * 32, n0 = blockIdx.x * 32;
    if (k0 >= K || n0 >= N) return;
    __shared__ float tile[32][33];
    const int tx = threadIdx.x, ty = threadIdx.y;   // 32 x 8
    #pragma unroll
    for (int i = 0; i < 32; i += 8) {
        int k = k0 + ty + i, n = n0 + tx;
        tile[ty + i][tx] = (k < K && n < N) ? W[(long)k * N + n] : 0.0f;
    }
    __syncthreads();
    #pragma unroll
    for (int i = 0; i < 32; i += 8) {
        int n = n0 + ty + i, k = k0 + tx;
        if (n < N && k < K) {
            float v = tile[tx][ty + i];
            bf16 h = __float2bfloat16(v);
            bf16 l = __float2bfloat16(v - __bfloat162float(h));
            oh[(long)n * K + k] = h;
            ol[(long)n * K + k] = l;
        }
    }
}

// ---------------- layer norm -> split bf16 output ----------------------------
__global__ void ln_kernel(const float* __restrict__ x, long ldx,
                          const float* __restrict__ gamma,
                          const float* __restrict__ beta,
                          const float* __restrict__ preBias,
                          const float* __restrict__ deg,
                          bf16* __restrict__ outH, bf16* __restrict__ outL,
                          long ldo, int colOff) {
    int n = blockIdx.x, t = threadIdx.x;
    float v = x[(long)n * ldx + t];
    if (deg) v = v / fmaxf(deg[n], 1.0f) + preBias[t];
    float s = v, s2 = v * v;
    #pragma unroll
    for (int o = 16; o; o >>= 1) {
        s  += __shfl_xor_sync(0xFFFFFFFFu, s,  o);
        s2 += __shfl_xor_sync(0xFFFFFFFFu, s2, o);
    }
    __shared__ float as[8], as2[8];
    int w = t >> 5, l = t & 31;
    if (l == 0) { as[w] = s; as2[w] = s2; }
    __syncthreads();
    float S = 0.f, S2 = 0.f;
    #pragma unroll
    for (int i = 0; i < 8; i++) { S += as[i]; S2 += as2[i]; }
    float mean = S * (1.0f / 256.0f);
    float var  = S2 * (1.0f / 256.0f) - mean * mean;
    float rstd = rsqrtf(var + 1e-5f);
    float r = (v - mean) * rstd * gamma[t] + beta[t];
    bf16 h = __float2bfloat16(r);
    bf16 lo = __float2bfloat16(r - __bfloat162float(h));
    long off = (long)n * ldo + colOff + t;
    outH[off] = h; outL[off] = lo;
}

// ============== HMMA split-bf16 GEMM: Out = op(A@B^T + bias) =================
// BM=128, BN=128, BK=32, 256 threads (8 warps = 2Mx4N, warp tile 64x32).
// 3-term split: D = Ah Bh + Al Bh + Ah Bl.  K % 32 == 0.
// 2 CTAs/SM for inter-CTA load/MMA overlap (80KB smem x2 fits 227KB).
#define PITCH 80                 // bytes per 32-bf16 row (conflict-free ldmatrix)
#define S_AH 0
#define S_AL 10240
#define S_BH 20480
#define S_BL 30720
#define STAGE 40960
#define GEMM_SMEM (2 * STAGE)

#define LDSM4(R, ADDR) \
    asm volatile("ldmatrix.sync.aligned.m8n8.x4.shared.b16 {%0,%1,%2,%3}, [%4];" \
                 : "=r"((R)[0]), "=r"((R)[1]), "=r"((R)[2]), "=r"((R)[3]) : "r"(ADDR))

#define MMA16816(C, A, B0, B1) \
    asm volatile("mma.sync.aligned.m16n8k16.row.col.f32.bf16.bf16.f32 " \
                 "{%0,%1,%2,%3}, {%4,%5,%6,%7}, {%8,%9}, {%0,%1,%2,%3};" \
                 : "+f"((C)[0]), "+f"((C)[1]), "+f"((C)[2]), "+f"((C)[3]) \
                 : "r"((A)[0]), "r"((A)[1]), "r"((A)[2]), "r"((A)[3]), \
                   "r"(B0), "r"(B1))

#define CP16(DST, SRC) \
    asm volatile("cp.async.cg.shared.global [%0], [%1], 16;" :: "r"(DST), "l"(SRC))

__global__ void __launch_bounds__(256, 2)
mma_gemm(const bf16* __restrict__ Ah, const bf16* __restrict__ Al, long lda,
         const bf16* __restrict__ Bh, const bf16* __restrict__ Bl, long ldb,
         const float* __restrict__ bias,
         float* __restrict__ Out, bf16* __restrict__ OutH, bf16* __restrict__ OutL,
         long ldo, int M, int K, int act, int accum) {
    extern __shared__ char smem[];
    const uint32_t sb = smem_u32(smem);
    const int tid  = threadIdx.x;
    const int lane = tid & 31;
    const int wid  = tid >> 5;
    const long bm = (long)blockIdx.y * 128;
    const long bn = (long)blockIdx.x * 128;
    const int wm = (wid & 1) * 64;       // warp M offset
    const int wn = (wid >> 1) * 32;      // warp N offset

    float acc[4][4][4];
    #pragma unroll
    for (int i = 0; i < 4; i++)
        #pragma unroll
        for (int j = 0; j < 4; j++)
            #pragma unroll
            for (int q = 0; q < 4; q++) acc[i][j][q] = 0.0f;

    const int nk = K >> 5;

    const int lrow0 = tid >> 2;          // 0..63 (+64 for odd sub-iter)
    const int lkc   = tid & 3;           // 16B chunk within 32-bf16 row

    #define ISSUE(kt) do {                                                     \
        const uint32_t st = sb + ((kt) & 1) * STAGE;                           \
        const long k0 = (long)(kt) << 5;                                       \
        _Pragma("unroll")                                                      \
        for (int i = 0; i < 8; i++) {                                          \
            const int part = i >> 1;                                           \
            const int row = lrow0 + (i & 1) * 64;                              \
            const uint32_t d = st + part * 10240 + row * PITCH + lkc * 16;     \
            const bf16* g;                                                     \
            if (part == 0)      g = Ah + (bm + row) * lda + k0 + lkc * 8;      \
            else if (part == 1) g = Al + (bm + row) * lda + k0 + lkc * 8;      \
            else if (part == 2) g = Bh + (bn + row) * ldb + k0 + lkc * 8;      \
            else                g = Bl + (bn + row) * ldb + k0 + lkc * 8;      \
            CP16(d, g);                                                        \
        }                                                                      \
        asm volatile("cp.async.commit_group;");                                \
    } while (0)

    ISSUE(0);

    const uint32_t a_off = (uint32_t)((wm + (lane & 15)) * PITCH + (lane >> 4) * 16);
    const uint32_t b_off = (uint32_t)((wn + (lane & 15)) * PITCH + (lane >> 4) * 16);

    for (int kt = 0; kt < nk; kt++) {
        if (kt + 1 < nk) {
            ISSUE(kt + 1);
            asm volatile("cp.async.wait_group 1;");
        } else {
            asm volatile("cp.async.wait_group 0;");
        }
        __syncthreads();
        const uint32_t st = sb + (kt & 1) * STAGE;
        #pragma unroll
        for (int h = 0; h < 2; h++) {
            uint32_t ah[4][4], al[4][4];
            #pragma unroll
            for (int mi = 0; mi < 4; mi++) {
                LDSM4(ah[mi], st + S_AH + a_off + mi * (16 * PITCH) + h * 32);
                LDSM4(al[mi], st + S_AL + a_off + mi * (16 * PITCH) + h * 32);
            }
            uint32_t bh[2][4], bl[2][4];
            #pragma unroll
            for (int jj = 0; jj < 2; jj++) {
                LDSM4(bh[jj], st + S_BH + b_off + jj * (16 * PITCH) + h * 32);
                LDSM4(bl[jj], st + S_BL + b_off + jj * (16 * PITCH) + h * 32);
            }
            #pragma unroll
            for (int mi = 0; mi < 4; mi++)
                #pragma unroll
                for (int j = 0; j < 4; j++) {
                    const int jj = j >> 1, jo = j & 1;
                    MMA16816(acc[mi][j], ah[mi], bh[jj][jo], bh[jj][2 + jo]);
                    MMA16816(acc[mi][j], al[mi], bh[jj][jo], bh[jj][2 + jo]);
                    MMA16816(acc[mi][j], ah[mi], bl[jj][jo], bl[jj][2 + jo]);
                }
        }
        __syncthreads();
    }

    // ---------------- epilogue ----------------
    const int r0 = lane >> 2;            // 0..7
    const int c0 = (lane & 3) * 2;       // 0,2,4,6
    float2 bv[4];
    if (bias) {
        #pragma unroll
        for (int j = 0; j < 4; j++)
            bv[j] = *(const float2*)&bias[bn + wn + j * 8 + c0];
    } else {
        #pragma unroll
        for (int j = 0; j < 4; j++) bv[j] = make_float2(0.f, 0.f);
    }
    #pragma unroll
    for (int mi = 0; mi < 4; mi++) {
        #pragma unroll
        for (int half = 0; half < 2; half++) {
            const long m = bm + wm + mi * 16 + r0 + half * 8;
            if (m >= M) continue;
            #pragma unroll
            for (int j = 0; j < 4; j++) {
                float x = acc[mi][j][half * 2 + 0] + bv[j].x;
                float y = acc[mi][j][half * 2 + 1] + bv[j].y;
                if (act) { x = silu_f(x); y = silu_f(y); }
                const long col = bn + wn + j * 8 + c0;
                if (OutH) {
                    bf16 hx = __float2bfloat16(x), hy = __float2bfloat16(y);
                    bf16 lx = __float2bfloat16(x - __bfloat162float(hx));
                    bf16 ly = __float2bfloat16(y - __bfloat162float(hy));
                    uint32_t hw = ((uint32_t)__bfloat16_as_ushort(hy) << 16) |
                                  __bfloat16_as_ushort(hx);
                    uint32_t lw = ((uint32_t)__bfloat16_as_ushort(ly) << 16) |
                                  __bfloat16_as_ushort(lx);
                    *(uint32_t*)(OutH + m * ldo + col) = hw;
                    *(uint32_t*)(OutL + m * ldo + col) = lw;
                } else {
                    float* o = Out + m * ldo + col;
                    if (accum) {
                        float2 old = *(const float2*)o;
                        x += old.x; y += old.y;
                    }
                    *(float2*)o = make_float2(x, y);
                }
            }
        }
    }
    #undef ISSUE
}

// ---------------- edge combine: silu(A[src]+B[dst]+C[e]) scatter into P -----
__global__ void edge_combine_kernel() {
    long idx = (long)blockIdx.x * blockDim.x + threadIdx.x;  // E * 64 items
    if (idx >= (long)N_EDGES * 64) return;
    int e = (int)(idx >> 6);
    int j = ((int)idx & 63) << 2;
    int s = g_src[e];
    int d = g_dst[e];
    float4 a = *(const float4*)&g_AB[(long)s * 512 + j];
    float4 b = *(const float4*)&g_AB[(long)d * 512 + 256 + j];
    float4 c = *(const float4*)&g_C[(long)e * 256 + j];
    float r0 = silu_f(a.x + b.x + c.x);
    float r1 = silu_f(a.y + b.y + c.y);
    float r2 = silu_f(a.z + b.z + c.z);
    float r3 = silu_f(a.w + b.w + c.w);
    float* p = &g_P[(long)d * 256 + j];
    asm volatile("red.global.add.v4.f32 [%0], {%1,%2,%3,%4};"
                 :: "l"(p), "f"(r0), "f"(r1), "f"(r2), "f"(r3) : "memory");
}

// ============================ launch =========================================
extern "C" void kernel_launch(void* const* d_in, const int* in_sizes, int n_in,
                              void* d_out, int out_size) {
    const float* node_state = (const float*)d_in[0];
    const float* edge_attr  = (const float*)d_in[1];
    const float* nn_g = (const float*)d_in[2];
    const float* nn_b = (const float*)d_in[3];
    const float* mn_g = (const float*)d_in[4];
    const float* mn_b = (const float*)d_in[5];
    const float* eW1  = (const float*)d_in[6];
    const float* eb1  = (const float*)d_in[7];
    const float* eW2  = (const float*)d_in[8];
    const float* eb2  = (const float*)d_in[9];
    const float* nW1  = (const float*)d_in[10];
    const float* nb1  = (const float*)d_in[11];
    const float* nW2  = (const float*)d_in[12];
    const float* nb2  = (const float*)d_in[13];
    const void*  eidx = d_in[14];
    float* h = (float*)d_out;

    cudaFuncSetAttribute(mma_gemm, cudaFuncAttributeMaxDynamicSharedMemorySize,
                         GEMM_SMEM);

    void *pYh, *pYl, *pAB, *pC, *pP, *pPh, *pPl, *pG, *pTh, *pTl,
         *pEah, *pEal, *pW1h, *pW1l, *pWch, *pWcl, *pW2h, *pW2l,
         *pN1h, *pN1l, *pN2h, *pN2l, *pdeg;
    cudaGetSymbolAddress(&pYh, g_Yh);   cudaGetSymbolAddress(&pYl, g_Yl);
    cudaGetSymbolAddress(&pAB, g_AB);   cudaGetSymbolAddress(&pC, g_C);
    cudaGetSymbolAddress(&pP, g_P);     cudaGetSymbolAddress(&pPh, g_Ph);
    cudaGetSymbolAddress(&pPl, g_Pl);   cudaGetSymbolAddress(&pG, g_G);
    cudaGetSymbolAddress(&pTh, g_Th);   cudaGetSymbolAddress(&pTl, g_Tl);
    cudaGetSymbolAddress(&pEah, g_eah); cudaGetSymbolAddress(&pEal, g_eal);
    cudaGetSymbolAddress(&pW1h, g_W1h); cudaGetSymbolAddress(&pW1l, g_W1l);
    cudaGetSymbolAddress(&pWch, g_Wch); cudaGetSymbolAddress(&pWcl, g_Wcl);
    cudaGetSymbolAddress(&pW2h, g_W2h); cudaGetSymbolAddress(&pW2l, g_W2l);
    cudaGetSymbolAddress(&pN1h, g_N1h); cudaGetSymbolAddress(&pN1l, g_N1l);
    cudaGetSymbolAddress(&pN2h, g_N2h); cudaGetSymbolAddress(&pN2l, g_N2l);
    cudaGetSymbolAddress(&pdeg, g_deg);

    bf16 *Yh=(bf16*)pYh, *Yl=(bf16*)pYl, *Ph=(bf16*)pPh, *Pl=(bf16*)pPl,
         *Th=(bf16*)pTh, *Tl=(bf16*)pTl, *Eah=(bf16*)pEah, *Eal=(bf16*)pEal,
         *W1h=(bf16*)pW1h, *W1l=(bf16*)pW1l, *Wch=(bf16*)pWch, *Wcl=(bf16*)pWcl,
         *W2h=(bf16*)pW2h, *W2l=(bf16*)pW2l, *N1h=(bf16*)pN1h, *N1l=(bf16*)pN1l,
         *N2h=(bf16*)pN2h, *N2l=(bf16*)pN2l;
    float *AB=(float*)pAB, *C=(float*)pC, *P=(float*)pP, *G=(float*)pG,
          *deg=(float*)pdeg;

    // ---- one-time prep ----
    cudaMemcpyAsync(h, node_state, (size_t)N_NODES * HDIM * sizeof(float),
                    cudaMemcpyDeviceToDevice, 0);
    cudaMemsetAsync(pdeg, 0, N_NODES * sizeof(float), 0);
    detect_idx_kernel<<<1, 64>>>((const long long*)eidx);
    convert_idx_kernel<<<(N_EDGES + 255) / 256, 256>>>(eidx);
    split_kernel<<<((long)N_EDGES * 64 + 255) / 256, 256>>>(edge_attr, Eah, Eal,
                                                            (long)N_EDGES * 64);
    tsplit_all<<<dim3(16, 16, 24), dim3(32, 8)>>>(eW1, eW2, nW1, nW2);

    const int MT = NPAD / 128;     // 157 M-tiles (node GEMMs)
    const int ET = N_EDGES / 128;  // 2500 M-tiles (edge GEMM)

    for (int i = 0; i < S_STEPS; i++) {
        // 1. hn = LN(h) -> Y[:, 0:256]
        ln_kernel<<<N_NODES, 256>>>(h, 256, nn_g + i * HDIM, nn_b + i * HDIM,
                                    nullptr, nullptr, Yh, Yl, 512, 0);
        // 2. AB = hn @ [W1a|W1b]   (M=20000, K=256, N=512)
        mma_gemm<<<dim3(4, MT), 256, GEMM_SMEM>>>(
            Yh, Yl, 512, W1h + (long)i * 512 * 256, W1l + (long)i * 512 * 256, 256,
            nullptr, AB, nullptr, nullptr, 512, N_NODES, 256, 0, 0);
        // 3. C = ea @ W1c + eb1    (M=320000, K=64, N=256)
        mma_gemm<<<dim3(2, ET), 256, GEMM_SMEM>>>(
            Eah, Eal, 64, Wch + (long)i * 256 * 64, Wcl + (long)i * 256 * 64, 64,
            eb1 + i * HDIM, C, nullptr, nullptr, 256, N_EDGES, 64, 0, 0);
        // 4. P = segsum_dst(silu(A[src]+B[dst]+C))
        cudaMemsetAsync(pP, 0, (size_t)N_NODES * 256 * sizeof(float), 0);
        edge_combine_kernel<<<((long)N_EDGES * 64) / 256, 256>>>();
        split_kernel<<<((long)N_NODES * 256 + 255) / 256, 256>>>(P, Ph, Pl,
                                                                 (long)N_NODES * 256);
        // 5. G = P @ eW2           (M=20000, K=256, N=256)
        mma_gemm<<<dim3(2, MT), 256, GEMM_SMEM>>>(
            Ph, Pl, 256, W2h + (long)i * 256 * 256, W2l + (long)i * 256 * 256, 256,
            nullptr, G, nullptr, nullptr, 256, N_NODES, 256, 0, 0);
        // 6. agg = LN(G/deg + eb2) -> Y[:, 256:512]
        ln_kernel<<<N_NODES, 256>>>(G, 256, mn_g + i * HDIM, mn_b + i * HDIM,
                                    eb2 + i * HDIM, deg, Yh, Yl, 512, 256);
        // 7. T = silu(y @ nW1 + nb1)  (M=20000, K=512, N=512, split bf16 out)
        mma_gemm<<<dim3(4, MT), 256, GEMM_SMEM>>>(
            Yh, Yl, 512, N1h + (long)i * 512 * 512, N1l + (long)i * 512 * 512, 512,
            nb1 + i * 512, nullptr, Th, Tl, 512, N_NODES, 512, 1, 0);
        // 8. h += T @ nW2 + nb2    (M=20000, K=512, N=256, fp32 accum)
        mma_gemm<<<dim3(2, MT), 256, GEMM_SMEM>>>(
            Th, Tl, 512, N2h + (long)i * 256 * 512, N2l + (long)i * 256 * 512, 512,
            nb2 + i * HDIM, h, nullptr, nullptr, 256, N_NODES, 512, 0, 1);
    }
}

// round 8
// speedup vs baseline: 1.6142x; 1.0036x over previous
#include <cuda_runtime.h>
#include <cuda_bf16.h>
#include <math.h>
#include <stdint.h>

#define N_NODES 20000
#define NPAD    20096            // 157 * 128
#define N_EDGES 320000
#define ECH     80000            // edges per overlap chunk (4 chunks)
#define NCH     4
#define HDIM    256
#define S_STEPS 4

typedef __nv_bfloat16 bf16;

// ---------------- device-global scratch (module-load allocated) -------------
__device__ bf16  g_Yh [NPAD * 512];      // [hn | agg] hi
__device__ bf16  g_Yl [NPAD * 512];      // [hn | agg] lo
__device__ float g_AB [NPAD * 512];      // [A | B] per node (fp32)
__device__ float g_C  [(size_t)N_EDGES * 256];  // ea@W1c + b1 per edge
__device__ float g_P  [NPAD * 256];      // segsum(silu(hidden))
__device__ bf16  g_Ph [NPAD * 256];
__device__ bf16  g_Pl [NPAD * 256];
__device__ float g_G  [NPAD * 256];      // P @ eW2
__device__ bf16  g_Th [NPAD * 512];      // silu(y@nW1+nb1) hi
__device__ bf16  g_Tl [NPAD * 512];
__device__ bf16  g_eah[(size_t)N_EDGES * 64];
__device__ bf16  g_eal[(size_t)N_EDGES * 64];
// transposed split weights, per step ([N,K] row-major)
__device__ bf16  g_W1h[4 * 512 * 256], g_W1l[4 * 512 * 256];
__device__ bf16  g_Wch[4 * 256 * 64],  g_Wcl[4 * 256 * 64];
__device__ bf16  g_W2h[4 * 256 * 256], g_W2l[4 * 256 * 256];
__device__ bf16  g_N1h[4 * 512 * 512], g_N1l[4 * 512 * 512];
__device__ bf16  g_N2h[4 * 256 * 512], g_N2l[4 * 256 * 512];
__device__ float g_deg[N_NODES];
__device__ int   g_src[N_EDGES];
__device__ int   g_dst[N_EDGES];
__device__ int   g_is64;

__device__ __forceinline__ float silu_f(float v) {
    return __fdividef(v, 1.0f + __expf(-v));
}

__device__ __forceinline__ uint32_t smem_u32(const void* p) {
    uint32_t a;
    asm("{ .reg .u64 t; cvta.to.shared.u64 t, %1; cvt.u32.u64 %0, t; }"
        : "=r"(a) : "l"(p));
    return a;
}

// ====================== small elementwise kernels ============================
// zero deg + detect index dtype, one launch
__global__ void zero_detect(const long long* __restrict__ p) {
    int i = blockIdx.x * blockDim.x + threadIdx.x;
    if (i < N_NODES) g_deg[i] = 0.0f;
    if (blockIdx.x == 0) {
        __shared__ int bad;
        if (threadIdx.x == 0) bad = 0;
        __syncthreads();
        if (threadIdx.x < 64) {
            long long v = p[threadIdx.x];
            if (v < 0 || v >= N_NODES) bad = 1;
        }
        __syncthreads();
        if (threadIdx.x == 0) g_is64 = bad ? 0 : 1;
    }
}

__global__ void convert_idx_kernel(const void* __restrict__ ei) {
    int e = blockIdx.x * blockDim.x + threadIdx.x;
    if (e >= N_EDGES) return;
    int s, d;
    if (g_is64) {
        const long long* p = (const long long*)ei;
        s = (int)p[e]; d = (int)p[N_EDGES + e];
    } else {
        const int* p = (const int*)ei;
        s = p[e]; d = p[N_EDGES + e];
    }
    g_src[e] = s; g_dst[e] = d;
    atomicAdd(&g_deg[d], 1.0f);
}

__global__ void split_kernel(const float* __restrict__ in,
                             bf16* __restrict__ oh, bf16* __restrict__ ol, long n) {
    long i = (long)blockIdx.x * blockDim.x + threadIdx.x;
    if (i >= n) return;
    float v = in[i];
    bf16 h = __float2bfloat16(v);
    bf16 l = __float2bfloat16(v - __bfloat162float(h));
    oh[i] = h; ol[i] = l;
}

// one launch transposes+splits ALL per-step weights.
__global__ void tsplit_all(const float* __restrict__ eW1,
                           const float* __restrict__ eW2,
                           const float* __restrict__ nW1,
                           const float* __restrict__ nW2) {
    const int z = blockIdx.z;
    const int step = z / 6, mat = z % 6;
    const float* W; int K, N; bf16 *oh, *ol;
    switch (mat) {
    case 0: W = eW1 + (long)step * 576 * 256;             K = 256; N = 256;
            oh = g_W1h + (long)step * 512 * 256;           ol = g_W1l + (long)step * 512 * 256;           break;
    case 1: W = eW1 + (long)step * 576 * 256 + 256 * 256; K = 256; N = 256;
            oh = g_W1h + (long)step * 512 * 256 + 256*256; ol = g_W1l + (long)step * 512 * 256 + 256*256; break;
    case 2: W = eW1 + (long)step * 576 * 256 + 512 * 256; K = 64;  N = 256;
            oh = g_Wch + (long)step * 256 * 64;            ol = g_Wcl + (long)step * 256 * 64;            break;
    case 3: W = eW2 + (long)step * 256 * 256;             K = 256; N = 256;
            oh = g_W2h + (long)step * 256 * 256;           ol = g_W2l + (long)step * 256 * 256;           break;
    case 4: W = nW1 + (long)step * 512 * 512;             K = 512; N = 512;
            oh = g_N1h + (long)step * 512 * 512;           ol = g_N1l + (long)step * 512 * 512;           break;
    default:W = nW2 + (long)step * 512 * 256;             K = 512; N = 256;
            oh = g_N2h + (long)step * 256 * 512;           ol = g_N2l + (long)step * 256 * 512;           break;
    }
    const int k0 = blockIdx.y * 32, n0 = blockIdx.x * 32;
    if (k0 >= K || n0 >= N) return;
    __shared__ float tile[32][33];
    const int tx = threadIdx.x, ty = threadIdx.y;   // 32 x 8
    #pragma unroll
    for (int i = 0; i < 32; i += 8) {
        int k = k0 + ty + i, n = n0 + tx;
        tile[ty + i][tx] = (k < K && n < N) ? W[(long)k * N + n] : 0.0f;
    }
    __syncthreads();
    #pragma unroll
    for (int i = 0; i < 32; i += 8) {
        int n = n0 + ty + i, k = k0 + tx;
        if (n < N && k < K) {
            float v = tile[tx][ty + i];
            bf16 h = __float2bfloat16(v);
            bf16 l = __float2bfloat16(v - __bfloat162float(h));
            oh[(long)n * K + k] = h;
            ol[(long)n * K + k] = l;
        }
    }
}

// ---------------- layer norm -> split bf16 output ----------------------------
__global__ void ln_kernel(const float* __restrict__ x, long ldx,
                          const float* __restrict__ gamma,
                          const float* __restrict__ beta,
                          const float* __restrict__ preBias,
                          const float* __restrict__ deg,
                          bf16* __restrict__ outH, bf16* __restrict__ outL,
                          long ldo, int colOff) {
    int n = blockIdx.x, t = threadIdx.x;
    float v = x[(long)n * ldx + t];
    if (deg) v = v / fmaxf(deg[n], 1.0f) + preBias[t];
    float s = v, s2 = v * v;
    #pragma unroll
    for (int o = 16; o; o >>= 1) {
        s  += __shfl_xor_sync(0xFFFFFFFFu, s,  o);
        s2 += __shfl_xor_sync(0xFFFFFFFFu, s2, o);
    }
    __shared__ float as[8], as2[8];
    int w = t >> 5, l = t & 31;
    if (l == 0) { as[w] = s; as2[w] = s2; }
    __syncthreads();
    float S = 0.f, S2 = 0.f;
    #pragma unroll
    for (int i = 0; i < 8; i++) { S += as[i]; S2 += as2[i]; }
    float mean = S * (1.0f / 256.0f);
    float var  = S2 * (1.0f / 256.0f) - mean * mean;
    float rstd = rsqrtf(var + 1e-5f);
    float r = (v - mean) * rstd * gamma[t] + beta[t];
    bf16 h = __float2bfloat16(r);
    bf16 lo = __float2bfloat16(r - __bfloat162float(h));
    long off = (long)n * ldo + colOff + t;
    outH[off] = h; outL[off] = lo;
}

// ============== HMMA split-bf16 GEMM: Out = op(A@B^T + bias) =================
// BM=128, BN=128, BK=32, 256 threads (8 warps = 2Mx4N, warp tile 64x32).
// 3-term split: D = Ah Bh + Al Bh + Ah Bl.  K % 32 == 0.  2 CTAs/SM.
#define PITCH 80
#define S_AH 0
#define S_AL 10240
#define S_BH 20480
#define S_BL 30720
#define STAGE 40960
#define GEMM_SMEM (2 * STAGE)

#define LDSM4(R, ADDR) \
    asm volatile("ldmatrix.sync.aligned.m8n8.x4.shared.b16 {%0,%1,%2,%3}, [%4];" \
                 : "=r"((R)[0]), "=r"((R)[1]), "=r"((R)[2]), "=r"((R)[3]) : "r"(ADDR))

#define MMA16816(C, A, B0, B1) \
    asm volatile("mma.sync.aligned.m16n8k16.row.col.f32.bf16.bf16.f32 " \
                 "{%0,%1,%2,%3}, {%4,%5,%6,%7}, {%8,%9}, {%0,%1,%2,%3};" \
                 : "+f"((C)[0]), "+f"((C)[1]), "+f"((C)[2]), "+f"((C)[3]) \
                 : "r"((A)[0]), "r"((A)[1]), "r"((A)[2]), "r"((A)[3]), \
                   "r"(B0), "r"(B1))

#define CP16(DST, SRC) \
    asm volatile("cp.async.cg.shared.global [%0], [%1], 16;" :: "r"(DST), "l"(SRC))

__global__ void __launch_bounds__(256, 2)
mma_gemm(const bf16* __restrict__ Ah, const bf16* __restrict__ Al, long lda,
         const bf16* __restrict__ Bh, const bf16* __restrict__ Bl, long ldb,
         const float* __restrict__ bias,
         float* __restrict__ Out, bf16* __restrict__ OutH, bf16* __restrict__ OutL,
         const float* __restrict__ AccIn,
         long ldo, int M, int K, int act, int accum) {
    extern __shared__ char smem[];
    const uint32_t sb = smem_u32(smem);
    const int tid  = threadIdx.x;
    const int lane = tid & 31;
    const int wid  = tid >> 5;
    const long bm = (long)blockIdx.y * 128;
    const long bn = (long)blockIdx.x * 128;
    const int wm = (wid & 1) * 64;
    const int wn = (wid >> 1) * 32;

    float acc[4][4][4];
    #pragma unroll
    for (int i = 0; i < 4; i++)
        #pragma unroll
        for (int j = 0; j < 4; j++)
            #pragma unroll
            for (int q = 0; q < 4; q++) acc[i][j][q] = 0.0f;

    const int nk = K >> 5;
    const int lrow0 = tid >> 2;
    const int lkc   = tid & 3;

    #define ISSUE(kt) do {                                                     \
        const uint32_t st = sb + ((kt) & 1) * STAGE;                           \
        const long k0 = (long)(kt) << 5;                                       \
        _Pragma("unroll")                                                      \
        for (int i = 0; i < 8; i++) {                                          \
            const int part = i >> 1;                                           \
            const int row = lrow0 + (i & 1) * 64;                              \
            const uint32_t d = st + part * 10240 + row * PITCH + lkc * 16;     \
            const bf16* g;                                                     \
            if (part == 0)      g = Ah + (bm + row) * lda + k0 + lkc * 8;      \
            else if (part == 1) g = Al + (bm + row) * lda + k0 + lkc * 8;      \
            else if (part == 2) g = Bh + (bn + row) * ldb + k0 + lkc * 8;      \
            else                g = Bl + (bn + row) * ldb + k0 + lkc * 8;      \
            CP16(d, g);                                                        \
        }                                                                      \
        asm volatile("cp.async.commit_group;");                                \
    } while (0)

    ISSUE(0);

    const uint32_t a_off = (uint32_t)((wm + (lane & 15)) * PITCH + (lane >> 4) * 16);
    const uint32_t b_off = (uint32_t)((wn + (lane & 15)) * PITCH + (lane >> 4) * 16);

    for (int kt = 0; kt < nk; kt++) {
        if (kt + 1 < nk) {
            ISSUE(kt + 1);
            asm volatile("cp.async.wait_group 1;");
        } else {
            asm volatile("cp.async.wait_group 0;");
        }
        __syncthreads();
        const uint32_t st = sb + (kt & 1) * STAGE;
        #pragma unroll
        for (int h = 0; h < 2; h++) {
            uint32_t ah[4][4], al[4][4];
            #pragma unroll
            for (int mi = 0; mi < 4; mi++) {
                LDSM4(ah[mi], st + S_AH + a_off + mi * (16 * PITCH) + h * 32);
                LDSM4(al[mi], st + S_AL + a_off + mi * (16 * PITCH) + h * 32);
            }
            uint32_t bh[2][4], bl[2][4];
            #pragma unroll
            for (int jj = 0; jj < 2; jj++) {
                LDSM4(bh[jj], st + S_BH + b_off + jj * (16 * PITCH) + h * 32);
                LDSM4(bl[jj], st + S_BL + b_off + jj * (16 * PITCH) + h * 32);
            }
            #pragma unroll
            for (int mi = 0; mi < 4; mi++)
                #pragma unroll
                for (int j = 0; j < 4; j++) {
                    const int jj = j >> 1, jo = j & 1;
                    MMA16816(acc[mi][j], ah[mi], bh[jj][jo], bh[jj][2 + jo]);
                    MMA16816(acc[mi][j], al[mi], bh[jj][jo], bh[jj][2 + jo]);
                    MMA16816(acc[mi][j], ah[mi], bl[jj][jo], bl[jj][2 + jo]);
                }
        }
        __syncthreads();
    }

    // ---------------- epilogue ----------------
    const int r0 = lane >> 2;
    const int c0 = (lane & 3) * 2;
    float2 bv[4];
    if (bias) {
        #pragma unroll
        for (int j = 0; j < 4; j++)
            bv[j] = *(const float2*)&bias[bn + wn + j * 8 + c0];
    } else {
        #pragma unroll
        for (int j = 0; j < 4; j++) bv[j] = make_float2(0.f, 0.f);
    }
    #pragma unroll
    for (int mi = 0; mi < 4; mi++) {
        #pragma unroll
        for (int half = 0; half < 2; half++) {
            const long m = bm + wm + mi * 16 + r0 + half * 8;
            if (m >= M) continue;
            #pragma unroll
            for (int j = 0; j < 4; j++) {
                float x = acc[mi][j][half * 2 + 0] + bv[j].x;
                float y = acc[mi][j][half * 2 + 1] + bv[j].y;
                if (act) { x = silu_f(x); y = silu_f(y); }
                const long col = bn + wn + j * 8 + c0;
                if (OutH) {
                    bf16 hx = __float2bfloat16(x), hy = __float2bfloat16(y);
                    bf16 lx = __float2bfloat16(x - __bfloat162float(hx));
                    bf16 ly = __float2bfloat16(y - __bfloat162float(hy));
                    uint32_t hw = ((uint32_t)__bfloat16_as_ushort(hy) << 16) |
                                  __bfloat16_as_ushort(hx);
                    uint32_t lw = ((uint32_t)__bfloat16_as_ushort(ly) << 16) |
                                  __bfloat16_as_ushort(lx);
                    *(uint32_t*)(OutH + m * ldo + col) = hw;
                    *(uint32_t*)(OutL + m * ldo + col) = lw;
                } else {
                    if (accum) {
                        float2 old = *(const float2*)(AccIn + m * ldo + col);
                        x += old.x; y += old.y;
                    }
                    *(float2*)(Out + m * ldo + col) = make_float2(x, y);
                }
            }
        }
    }
    #undef ISSUE
}

// ---------------- edge combine: silu(A[src]+B[dst]+C[e]) scatter into P -----
__global__ void edge_combine_kernel(int ebase) {
    long idx = (long)blockIdx.x * blockDim.x + threadIdx.x;  // ECH * 64 items
    int e = ebase + (int)(idx >> 6);
    int j = ((int)idx & 63) << 2;
    int s = g_src[e];
    int d = g_dst[e];
    float4 a = *(const float4*)&g_AB[(long)s * 512 + j];
    float4 b = *(const float4*)&g_AB[(long)d * 512 + 256 + j];
    float4 c = *(const float4*)&g_C[(long)e * 256 + j];
    float r0 = silu_f(a.x + b.x + c.x);
    float r1 = silu_f(a.y + b.y + c.y);
    float r2 = silu_f(a.z + b.z + c.z);
    float r3 = silu_f(a.w + b.w + c.w);
    float* p = &g_P[(long)d * 256 + j];
    asm volatile("red.global.add.v4.f32 [%0], {%1,%2,%3,%4};"
                 :: "l"(p), "f"(r0), "f"(r1), "f"(r2), "f"(r3) : "memory");
}

// ============================ launch =========================================
extern "C" void kernel_launch(void* const* d_in, const int* in_sizes, int n_in,
                              void* d_out, int out_size) {
    const float* node_state = (const float*)d_in[0];
    const float* edge_attr  = (const float*)d_in[1];
    const float* nn_g = (const float*)d_in[2];
    const float* nn_b = (const float*)d_in[3];
    const float* mn_g = (const float*)d_in[4];
    const float* mn_b = (const float*)d_in[5];
    const float* eW1  = (const float*)d_in[6];
    const float* eb1  = (const float*)d_in[7];
    const float* eW2  = (const float*)d_in[8];
    const float* eb2  = (const float*)d_in[9];
    const float* nW1  = (const float*)d_in[10];
    const float* nb1  = (const float*)d_in[11];
    const float* nW2  = (const float*)d_in[12];
    const float* nb2  = (const float*)d_in[13];
    const void*  eidx = d_in[14];
    float* h = (float*)d_out;

    // one-time infra (streams/events are handles, not device memory)
    static bool inited = false;
    static cudaStream_t s1, s2;
    static cudaEvent_t evFork, evG2, evComb, evG3[NCH];
    if (!inited) {
        cudaStreamCreateWithFlags(&s1, cudaStreamNonBlocking);
        cudaStreamCreateWithFlags(&s2, cudaStreamNonBlocking);
        cudaEventCreateWithFlags(&evFork, cudaEventDisableTiming);
        cudaEventCreateWithFlags(&evG2,   cudaEventDisableTiming);
        cudaEventCreateWithFlags(&evComb, cudaEventDisableTiming);
        for (int k = 0; k < NCH; k++)
            cudaEventCreateWithFlags(&evG3[k], cudaEventDisableTiming);
        cudaFuncSetAttribute(mma_gemm, cudaFuncAttributeMaxDynamicSharedMemorySize,
                             GEMM_SMEM);
        inited = true;
    }

    void *pYh, *pYl, *pAB, *pC, *pP, *pPh, *pPl, *pG, *pTh, *pTl,
         *pEah, *pEal, *pW1h, *pW1l, *pWch, *pWcl, *pW2h, *pW2l,
         *pN1h, *pN1l, *pN2h, *pN2l, *pdeg;
    cudaGetSymbolAddress(&pYh, g_Yh);   cudaGetSymbolAddress(&pYl, g_Yl);
    cudaGetSymbolAddress(&pAB, g_AB);   cudaGetSymbolAddress(&pC, g_C);
    cudaGetSymbolAddress(&pP, g_P);     cudaGetSymbolAddress(&pPh, g_Ph);
    cudaGetSymbolAddress(&pPl, g_Pl);   cudaGetSymbolAddress(&pG, g_G);
    cudaGetSymbolAddress(&pTh, g_Th);   cudaGetSymbolAddress(&pTl, g_Tl);
    cudaGetSymbolAddress(&pEah, g_eah); cudaGetSymbolAddress(&pEal, g_eal);
    cudaGetSymbolAddress(&pW1h, g_W1h); cudaGetSymbolAddress(&pW1l, g_W1l);
    cudaGetSymbolAddress(&pWch, g_Wch); cudaGetSymbolAddress(&pWcl, g_Wcl);
    cudaGetSymbolAddress(&pW2h, g_W2h); cudaGetSymbolAddress(&pW2l, g_W2l);
    cudaGetSymbolAddress(&pN1h, g_N1h); cudaGetSymbolAddress(&pN1l, g_N1l);
    cudaGetSymbolAddress(&pN2h, g_N2h); cudaGetSymbolAddress(&pN2l, g_N2l);
    cudaGetSymbolAddress(&pdeg, g_deg);

    bf16 *Yh=(bf16*)pYh, *Yl=(bf16*)pYl, *Ph=(bf16*)pPh, *Pl=(bf16*)pPl,
         *Th=(bf16*)pTh, *Tl=(bf16*)pTl, *Eah=(bf16*)pEah, *Eal=(bf16*)pEal,
         *W1h=(bf16*)pW1h, *W1l=(bf16*)pW1l, *Wch=(bf16*)pWch, *Wcl=(bf16*)pWcl,
         *W2h=(bf16*)pW2h, *W2l=(bf16*)pW2l, *N1h=(bf16*)pN1h, *N1l=(bf16*)pN1l,
         *N2h=(bf16*)pN2h, *N2l=(bf16*)pN2l;
    float *AB=(float*)pAB, *C=(float*)pC, *P=(float*)pP, *G=(float*)pG,
          *deg=(float*)pdeg;

    // ---- prep: exactly 4 kernel launches before the main loop ----
    zero_detect<<<(N_NODES + 255) / 256, 256>>>((const long long*)eidx);
    convert_idx_kernel<<<(N_EDGES + 255) / 256, 256>>>(eidx);
    split_kernel<<<((long)N_EDGES * 64 + 255) / 256, 256>>>(edge_attr, Eah, Eal,
                                                            (long)N_EDGES * 64);
    tsplit_all<<<dim3(16, 16, 24), dim3(32, 8)>>>(eW1, eW2, nW1, nW2);

    const int MT = NPAD / 128;     // 157 M-tiles (node GEMMs)
    const int CT = ECH / 128;      // 625 M-tiles per edge chunk

    for (int i = 0; i < S_STEPS; i++) {
        const float* hin = (i == 0) ? node_state : h;

        // fork edge GEMM chunks onto s1 (depends only on weights + Eah)
        cudaEventRecord(evFork, 0);
        cudaStreamWaitEvent(s1, evFork, 0);
        for (int k = 0; k < NCH; k++) {
            const size_t cb = (size_t)k * ECH;
            mma_gemm<<<dim3(2, CT), 256, GEMM_SMEM, s1>>>(
                Eah + cb * 64, Eal + cb * 64, 64,
                Wch + (long)i * 256 * 64, Wcl + (long)i * 256 * 64, 64,
                eb1 + i * HDIM, C + cb * 256, nullptr, nullptr, nullptr, 256,
                ECH, 64, 0, 0);
            cudaEventRecord(evG3[k], s1);
        }

        // main stream: ln -> memset P -> GEMM-2
        ln_kernel<<<N_NODES, 256>>>(hin, 256, nn_g + i * HDIM, nn_b + i * HDIM,
                                    nullptr, nullptr, Yh, Yl, 512, 0);
        cudaMemsetAsync(pP, 0, (size_t)N_NODES * 256 * sizeof(float), 0);
        mma_gemm<<<dim3(4, MT), 256, GEMM_SMEM>>>(
            Yh, Yl, 512, W1h + (long)i * 512 * 256, W1l + (long)i * 512 * 256, 256,
            nullptr, AB, nullptr, nullptr, nullptr, 512, N_NODES, 256, 0, 0);
        cudaEventRecord(evG2, 0);

        // combine chunks on s2: overlap with later G3 chunks / G2 tail
        cudaStreamWaitEvent(s2, evG2, 0);
        for (int k = 0; k < NCH; k++) {
            cudaStreamWaitEvent(s2, evG3[k], 0);
            edge_combine_kernel<<<((long)ECH * 64) / 256, 256, 0, s2>>>(k * ECH);
        }
        cudaEventRecord(evComb, s2);
        cudaStreamWaitEvent(0, evComb, 0);

        // back on main stream
        split_kernel<<<((long)N_NODES * 256 + 255) / 256, 256>>>(P, Ph, Pl,
                                                                 (long)N_NODES * 256);
        mma_gemm<<<dim3(2, MT), 256, GEMM_SMEM>>>(
            Ph, Pl, 256, W2h + (long)i * 256 * 256, W2l + (long)i * 256 * 256, 256,
            nullptr, G, nullptr, nullptr, nullptr, 256, N_NODES, 256, 0, 0);
        ln_kernel<<<N_NODES, 256>>>(G, 256, mn_g + i * HDIM, mn_b + i * HDIM,
                                    eb2 + i * HDIM, deg, Yh, Yl, 512, 256);
        mma_gemm<<<dim3(4, MT), 256, GEMM_SMEM>>>(
            Yh, Yl, 512, N1h + (long)i * 512 * 512, N1l + (long)i * 512 * 512, 512,
            nb1 + i * 512, nullptr, Th, Tl, nullptr, 512, N_NODES, 512, 1, 0);
        mma_gemm<<<dim3(2, MT), 256, GEMM_SMEM>>>(
            Th, Tl, 512, N2h + (long)i * 256 * 512, N2l + (long)i * 256 * 512, 512,
            nb2 + i * HDIM, h, nullptr, nullptr, hin, 256, N_NODES, 512, 0, 1);
    }
}

// round 9
// speedup vs baseline: 1.9535x; 1.2102x over previous
#include <cuda_runtime.h>
#include <cuda_fp16.h>
#include <math.h>
#include <stdint.h>

#define N_NODES 20000
#define NPAD    20096            // 157 * 128
#define N_EDGES 320000
#define ECH     80000            // edges per overlap chunk (4 chunks)
#define NCH     4
#define HDIM    256
#define S_STEPS 4

typedef __half h16;

// ---------------- device-global scratch (module-load allocated) -------------
__device__ h16   g_Y  [NPAD * 512];      // [hn | agg] fp16
__device__ float g_AB [NPAD * 512];      // [A | B] per node (fp32)
__device__ float g_C  [(size_t)N_EDGES * 256];  // ea@W1c + b1 per edge
__device__ float g_P  [NPAD * 256];      // segsum(silu(hidden))
__device__ h16   g_Pf [NPAD * 256];      // P as fp16
__device__ float g_G  [NPAD * 256];      // P @ eW2
__device__ h16   g_T  [NPAD * 512];      // silu(y@nW1+nb1) fp16
__device__ h16   g_ea [(size_t)N_EDGES * 64];
// transposed split weights, per step ([N,K] row-major, fp16 hi/lo)
__device__ h16   g_W1h[4 * 512 * 256], g_W1l[4 * 512 * 256];
__device__ h16   g_Wch[4 * 256 * 64],  g_Wcl[4 * 256 * 64];
__device__ h16   g_W2h[4 * 256 * 256], g_W2l[4 * 256 * 256];
__device__ h16   g_N1h[4 * 512 * 512], g_N1l[4 * 512 * 512];
__device__ h16   g_N2h[4 * 256 * 512], g_N2l[4 * 256 * 512];
__device__ float g_deg[N_NODES];
__device__ int   g_src[N_EDGES];
__device__ int   g_dst[N_EDGES];
__device__ int   g_is64;

__device__ __forceinline__ float silu_f(float v) {
    return __fdividef(v, 1.0f + __expf(-v));
}

__device__ __forceinline__ uint32_t smem_u32(const void* p) {
    uint32_t a;
    asm("{ .reg .u64 t; cvta.to.shared.u64 t, %1; cvt.u32.u64 %0, t; }"
        : "=r"(a) : "l"(p));
    return a;
}

// ====================== small elementwise kernels ============================
__global__ void zero_detect(const long long* __restrict__ p) {
    int i = blockIdx.x * blockDim.x + threadIdx.x;
    if (i < N_NODES) g_deg[i] = 0.0f;
    if (blockIdx.x == 0) {
        __shared__ int bad;
        if (threadIdx.x == 0) bad = 0;
        __syncthreads();
        if (threadIdx.x < 64) {
            long long v = p[threadIdx.x];
            if (v < 0 || v >= N_NODES) bad = 1;
        }
        __syncthreads();
        if (threadIdx.x == 0) g_is64 = bad ? 0 : 1;
    }
}

__global__ void convert_idx_kernel(const void* __restrict__ ei) {
    int e = blockIdx.x * blockDim.x + threadIdx.x;
    if (e >= N_EDGES) return;
    int s, d;
    if (g_is64) {
        const long long* p = (const long long*)ei;
        s = (int)p[e]; d = (int)p[N_EDGES + e];
    } else {
        const int* p = (const int*)ei;
        s = p[e]; d = p[N_EDGES + e];
    }
    g_src[e] = s; g_dst[e] = d;
    atomicAdd(&g_deg[d], 1.0f);
}

// fp32 -> single fp16 convert
__global__ void cvt_kernel(const float* __restrict__ in,
                           h16* __restrict__ out, long n) {
    long i = (long)blockIdx.x * blockDim.x + threadIdx.x;
    if (i >= n) return;
    out[i] = __float2half(in[i]);
}

// one launch transposes+splits ALL per-step weights (fp16 hi/lo).
__global__ void tsplit_all(const float* __restrict__ eW1,
                           const float* __restrict__ eW2,
                           const float* __restrict__ nW1,
                           const float* __restrict__ nW2) {
    const int z = blockIdx.z;
    const int step = z / 6, mat = z % 6;
    const float* W; int K, N; h16 *oh, *ol;
    switch (mat) {
    case 0: W = eW1 + (long)step * 576 * 256;             K = 256; N = 256;
            oh = g_W1h + (long)step * 512 * 256;           ol = g_W1l + (long)step * 512 * 256;           break;
    case 1: W = eW1 + (long)step * 576 * 256 + 256 * 256; K = 256; N = 256;
            oh = g_W1h + (long)step * 512 * 256 + 256*256; ol = g_W1l + (long)step * 512 * 256 + 256*256; break;
    case 2: W = eW1 + (long)step * 576 * 256 + 512 * 256; K = 64;  N = 256;
            oh = g_Wch + (long)step * 256 * 64;            ol = g_Wcl + (long)step * 256 * 64;            break;
    case 3: W = eW2 + (long)step * 256 * 256;             K = 256; N = 256;
            oh = g_W2h + (long)step * 256 * 256;           ol = g_W2l + (long)step * 256 * 256;           break;
    case 4: W = nW1 + (long)step * 512 * 512;             K = 512; N = 512;
            oh = g_N1h + (long)step * 512 * 512;           ol = g_N1l + (long)step * 512 * 512;           break;
    default:W = nW2 + (long)step * 512 * 256;             K = 512; N = 256;
            oh = g_N2h + (long)step * 256 * 512;           ol = g_N2l + (long)step * 256 * 512;           break;
    }
    const int k0 = blockIdx.y * 32, n0 = blockIdx.x * 32;
    if (k0 >= K || n0 >= N) return;
    __shared__ float tile[32][33];
    const int tx = threadIdx.x, ty = threadIdx.y;   // 32 x 8
    #pragma unroll
    for (int i = 0; i < 32; i += 8) {
        int k = k0 + ty + i, n = n0 + tx;
        tile[ty + i][tx] = (k < K && n < N) ? W[(long)k * N + n] : 0.0f;
    }
    __syncthreads();
    #pragma unroll
    for (int i = 0; i < 32; i += 8) {
        int n = n0 + ty + i, k = k0 + tx;
        if (n < N && k < K) {
            float v = tile[tx][ty + i];
            h16 h = __float2half(v);
            h16 l = __float2half(v - __half2float(h));
            oh[(long)n * K + k] = h;
            ol[(long)n * K + k] = l;
        }
    }
}

// ---------------- layer norm -> fp16 output ----------------------------------
__global__ void ln_kernel(const float* __restrict__ x, long ldx,
                          const float* __restrict__ gamma,
                          const float* __restrict__ beta,
                          const float* __restrict__ preBias,
                          const float* __restrict__ deg,
                          h16* __restrict__ out, long ldo, int colOff) {
    int n = blockIdx.x, t = threadIdx.x;
    float v = x[(long)n * ldx + t];
    if (deg) v = v / fmaxf(deg[n], 1.0f) + preBias[t];
    float s = v, s2 = v * v;
    #pragma unroll
    for (int o = 16; o; o >>= 1) {
        s  += __shfl_xor_sync(0xFFFFFFFFu, s,  o);
        s2 += __shfl_xor_sync(0xFFFFFFFFu, s2, o);
    }
    __shared__ float as[8], as2[8];
    int w = t >> 5, l = t & 31;
    if (l == 0) { as[w] = s; as2[w] = s2; }
    __syncthreads();
    float S = 0.f, S2 = 0.f;
    #pragma unroll
    for (int i = 0; i < 8; i++) { S += as[i]; S2 += as2[i]; }
    float mean = S * (1.0f / 256.0f);
    float var  = S2 * (1.0f / 256.0f) - mean * mean;
    float rstd = rsqrtf(var + 1e-5f);
    float r = (v - mean) * rstd * gamma[t] + beta[t];
    out[(long)n * ldo + colOff + t] = __float2half(r);
}

// ====== HMMA fp16 GEMM, weights split: Out = op(A@(Wh+Wl)^T + bias) ==========
// BM=128, BN=128, BK=32, 256 threads (8 warps = 2Mx4N, warp tile 64x32).
// 2 MMA terms: D = A Wh + A Wl.  K % 32 == 0.  2 CTAs/SM.
#define PITCH 80
#define S_A  0
#define S_BH 10240
#define S_BL 20480
#define STAGE 30720
#define GEMM_SMEM (2 * STAGE)

#define LDSM4(R, ADDR) \
    asm volatile("ldmatrix.sync.aligned.m8n8.x4.shared.b16 {%0,%1,%2,%3}, [%4];" \
                 : "=r"((R)[0]), "=r"((R)[1]), "=r"((R)[2]), "=r"((R)[3]) : "r"(ADDR))

#define MMA16816(C, A, B0, B1) \
    asm volatile("mma.sync.aligned.m16n8k16.row.col.f32.f16.f16.f32 " \
                 "{%0,%1,%2,%3}, {%4,%5,%6,%7}, {%8,%9}, {%0,%1,%2,%3};" \
                 : "+f"((C)[0]), "+f"((C)[1]), "+f"((C)[2]), "+f"((C)[3]) \
                 : "r"((A)[0]), "r"((A)[1]), "r"((A)[2]), "r"((A)[3]), \
                   "r"(B0), "r"(B1))

#define CP16(DST, SRC) \
    asm volatile("cp.async.cg.shared.global [%0], [%1], 16;" :: "r"(DST), "l"(SRC))

__global__ void __launch_bounds__(256, 2)
mma_gemm(const h16* __restrict__ A, long lda,
         const h16* __restrict__ Bh, const h16* __restrict__ Bl, long ldb,
         const float* __restrict__ bias,
         float* __restrict__ Out, h16* __restrict__ OutF,
         const float* __restrict__ AccIn,
         long ldo, int M, int K, int act, int accum) {
    extern __shared__ char smem[];
    const uint32_t sb = smem_u32(smem);
    const int tid  = threadIdx.x;
    const int lane = tid & 31;
    const int wid  = tid >> 5;
    const long bm = (long)blockIdx.y * 128;
    const long bn = (long)blockIdx.x * 128;
    const int wm = (wid & 1) * 64;
    const int wn = (wid >> 1) * 32;

    float acc[4][4][4];
    #pragma unroll
    for (int i = 0; i < 4; i++)
        #pragma unroll
        for (int j = 0; j < 4; j++)
            #pragma unroll
            for (int q = 0; q < 4; q++) acc[i][j][q] = 0.0f;

    const int nk = K >> 5;
    const int lrow0 = tid >> 2;          // 0..63 (+64 for odd sub-iter)
    const int lkc   = tid & 3;           // 16B chunk within 32-fp16 row

    #define ISSUE(kt) do {                                                     \
        const uint32_t st = sb + ((kt) & 1) * STAGE;                           \
        const long k0 = (long)(kt) << 5;                                       \
        _Pragma("unroll")                                                      \
        for (int i = 0; i < 6; i++) {                                          \
            const int part = i >> 1;                                           \
            const int row = lrow0 + (i & 1) * 64;                              \
            const uint32_t d = st + part * 10240 + row * PITCH + lkc * 16;     \
            const h16* g;                                                      \
            if (part == 0)      g = A  + (bm + row) * lda + k0 + lkc * 8;      \
            else if (part == 1) g = Bh + (bn + row) * ldb + k0 + lkc * 8;      \
            else                g = Bl + (bn + row) * ldb + k0 + lkc * 8;      \
            CP16(d, g);                                                        \
        }                                                                      \
        asm volatile("cp.async.commit_group;");                                \
    } while (0)

    ISSUE(0);

    const uint32_t a_off = (uint32_t)((wm + (lane & 15)) * PITCH + (lane >> 4) * 16);
    const uint32_t b_off = (uint32_t)((wn + (lane & 15)) * PITCH + (lane >> 4) * 16);

    for (int kt = 0; kt < nk; kt++) {
        if (kt + 1 < nk) {
            ISSUE(kt + 1);
            asm volatile("cp.async.wait_group 1;");
        } else {
            asm volatile("cp.async.wait_group 0;");
        }
        __syncthreads();
        const uint32_t st = sb + (kt & 1) * STAGE;
        #pragma unroll
        for (int h = 0; h < 2; h++) {
            uint32_t a[4][4];
            #pragma unroll
            for (int mi = 0; mi < 4; mi++)
                LDSM4(a[mi], st + S_A + a_off + mi * (16 * PITCH) + h * 32);
            uint32_t bh[2][4], bl[2][4];
            #pragma unroll
            for (int jj = 0; jj < 2; jj++) {
                LDSM4(bh[jj], st + S_BH + b_off + jj * (16 * PITCH) + h * 32);
                LDSM4(bl[jj], st + S_BL + b_off + jj * (16 * PITCH) + h * 32);
            }
            #pragma unroll
            for (int mi = 0; mi < 4; mi++)
                #pragma unroll
                for (int j = 0; j < 4; j++) {
                    const int jj = j >> 1, jo = j & 1;
                    MMA16816(acc[mi][j], a[mi], bh[jj][jo], bh[jj][2 + jo]);
                    MMA16816(acc[mi][j], a[mi], bl[jj][jo], bl[jj][2 + jo]);
                }
        }
        __syncthreads();
    }

    // ---------------- epilogue ----------------
    const int r0 = lane >> 2;
    const int c0 = (lane & 3) * 2;
    float2 bv[4];
    if (bias) {
        #pragma unroll
        for (int j = 0; j < 4; j++)
            bv[j] = *(const float2*)&bias[bn + wn + j * 8 + c0];
    } else {
        #pragma unroll
        for (int j = 0; j < 4; j++) bv[j] = make_float2(0.f, 0.f);
    }
    #pragma unroll
    for (int mi = 0; mi < 4; mi++) {
        #pragma unroll
        for (int half = 0; half < 2; half++) {
            const long m = bm + wm + mi * 16 + r0 + half * 8;
            if (m >= M) continue;
            #pragma unroll
            for (int j = 0; j < 4; j++) {
                float x = acc[mi][j][half * 2 + 0] + bv[j].x;
                float y = acc[mi][j][half * 2 + 1] + bv[j].y;
                if (act) { x = silu_f(x); y = silu_f(y); }
                const long col = bn + wn + j * 8 + c0;
                if (OutF) {
                    uint32_t hw = ((uint32_t)__half_as_ushort(__float2half(y)) << 16) |
                                  __half_as_ushort(__float2half(x));
                    *(uint32_t*)(OutF + m * ldo + col) = hw;
                } else {
                    if (accum) {
                        float2 old = *(const float2*)(AccIn + m * ldo + col);
                        x += old.x; y += old.y;
                    }
                    *(float2*)(Out + m * ldo + col) = make_float2(x, y);
                }
            }
        }
    }
    #undef ISSUE
}

// ---------------- edge combine: silu(A[src]+B[dst]+C[e]) scatter into P -----
__global__ void edge_combine_kernel(int ebase) {
    long idx = (long)blockIdx.x * blockDim.x + threadIdx.x;  // ECH * 64 items
    int e = ebase + (int)(idx >> 6);
    int j = ((int)idx & 63) << 2;
    int s = g_src[e];
    int d = g_dst[e];
    float4 a = *(const float4*)&g_AB[(long)s * 512 + j];
    float4 b = *(const float4*)&g_AB[(long)d * 512 + 256 + j];
    float4 c = *(const float4*)&g_C[(long)e * 256 + j];
    float r0 = silu_f(a.x + b.x + c.x);
    float r1 = silu_f(a.y + b.y + c.y);
    float r2 = silu_f(a.z + b.z + c.z);
    float r3 = silu_f(a.w + b.w + c.w);
    float* p = &g_P[(long)d * 256 + j];
    asm volatile("red.global.add.v4.f32 [%0], {%1,%2,%3,%4};"
                 :: "l"(p), "f"(r0), "f"(r1), "f"(r2), "f"(r3) : "memory");
}

// ============================ launch =========================================
extern "C" void kernel_launch(void* const* d_in, const int* in_sizes, int n_in,
                              void* d_out, int out_size) {
    const float* node_state = (const float*)d_in[0];
    const float* edge_attr  = (const float*)d_in[1];
    const float* nn_g = (const float*)d_in[2];
    const float* nn_b = (const float*)d_in[3];
    const float* mn_g = (const float*)d_in[4];
    const float* mn_b = (const float*)d_in[5];
    const float* eW1  = (const float*)d_in[6];
    const float* eb1  = (const float*)d_in[7];
    const float* eW2  = (const float*)d_in[8];
    const float* eb2  = (const float*)d_in[9];
    const float* nW1  = (const float*)d_in[10];
    const float* nb1  = (const float*)d_in[11];
    const float* nW2  = (const float*)d_in[12];
    const float* nb2  = (const float*)d_in[13];
    const void*  eidx = d_in[14];
    float* h = (float*)d_out;

    static bool inited = false;
    static cudaStream_t s1, s2;
    static cudaEvent_t evFork, evG2, evComb, evG3[NCH];
    if (!inited) {
        cudaStreamCreateWithFlags(&s1, cudaStreamNonBlocking);
        cudaStreamCreateWithFlags(&s2, cudaStreamNonBlocking);
        cudaEventCreateWithFlags(&evFork, cudaEventDisableTiming);
        cudaEventCreateWithFlags(&evG2,   cudaEventDisableTiming);
        cudaEventCreateWithFlags(&evComb, cudaEventDisableTiming);
        for (int k = 0; k < NCH; k++)
            cudaEventCreateWithFlags(&evG3[k], cudaEventDisableTiming);
        cudaFuncSetAttribute(mma_gemm, cudaFuncAttributeMaxDynamicSharedMemorySize,
                             GEMM_SMEM);
        inited = true;
    }

    void *pY, *pAB, *pC, *pP, *pPf, *pG, *pT, *pEa,
         *pW1h, *pW1l, *pWch, *pWcl, *pW2h, *pW2l,
         *pN1h, *pN1l, *pN2h, *pN2l, *pdeg;
    cudaGetSymbolAddress(&pY, g_Y);     cudaGetSymbolAddress(&pAB, g_AB);
    cudaGetSymbolAddress(&pC, g_C);     cudaGetSymbolAddress(&pP, g_P);
    cudaGetSymbolAddress(&pPf, g_Pf);   cudaGetSymbolAddress(&pG, g_G);
    cudaGetSymbolAddress(&pT, g_T);     cudaGetSymbolAddress(&pEa, g_ea);
    cudaGetSymbolAddress(&pW1h, g_W1h); cudaGetSymbolAddress(&pW1l, g_W1l);
    cudaGetSymbolAddress(&pWch, g_Wch); cudaGetSymbolAddress(&pWcl, g_Wcl);
    cudaGetSymbolAddress(&pW2h, g_W2h); cudaGetSymbolAddress(&pW2l, g_W2l);
    cudaGetSymbolAddress(&pN1h, g_N1h); cudaGetSymbolAddress(&pN1l, g_N1l);
    cudaGetSymbolAddress(&pN2h, g_N2h); cudaGetSymbolAddress(&pN2l, g_N2l);
    cudaGetSymbolAddress(&pdeg, g_deg);

    h16 *Y=(h16*)pY, *Pf=(h16*)pPf, *T=(h16*)pT, *Ea=(h16*)pEa,
        *W1h=(h16*)pW1h, *W1l=(h16*)pW1l, *Wch=(h16*)pWch, *Wcl=(h16*)pWcl,
        *W2h=(h16*)pW2h, *W2l=(h16*)pW2l, *N1h=(h16*)pN1h, *N1l=(h16*)pN1l,
        *N2h=(h16*)pN2h, *N2l=(h16*)pN2l;
    float *AB=(float*)pAB, *C=(float*)pC, *P=(float*)pP, *G=(float*)pG,
          *deg=(float*)pdeg;

    // ---- prep: 4 kernel launches ----
    zero_detect<<<(N_NODES + 255) / 256, 256>>>((const long long*)eidx);
    convert_idx_kernel<<<(N_EDGES + 255) / 256, 256>>>(eidx);
    cvt_kernel<<<((long)N_EDGES * 64 + 255) / 256, 256>>>(edge_attr, Ea,
                                                          (long)N_EDGES * 64);
    tsplit_all<<<dim3(16, 16, 24), dim3(32, 8)>>>(eW1, eW2, nW1, nW2);

    const int MT = NPAD / 128;     // 157 M-tiles (node GEMMs)
    const int CT = ECH / 128;      // 625 M-tiles per edge chunk

    for (int i = 0; i < S_STEPS; i++) {
        const float* hin = (i == 0) ? node_state : h;

        // fork edge GEMM chunks onto s1
        cudaEventRecord(evFork, 0);
        cudaStreamWaitEvent(s1, evFork, 0);
        for (int k = 0; k < NCH; k++) {
            const size_t cb = (size_t)k * ECH;
            mma_gemm<<<dim3(2, CT), 256, GEMM_SMEM, s1>>>(
                Ea + cb * 64, 64,
                Wch + (long)i * 256 * 64, Wcl + (long)i * 256 * 64, 64,
                eb1 + i * HDIM, C + cb * 256, nullptr, nullptr, 256,
                ECH, 64, 0, 0);
            cudaEventRecord(evG3[k], s1);
        }

        // main stream: ln -> memset P -> GEMM-2
        ln_kernel<<<N_NODES, 256>>>(hin, 256, nn_g + i * HDIM, nn_b + i * HDIM,
                                    nullptr, nullptr, Y, 512, 0);
        cudaMemsetAsync(pP, 0, (size_t)N_NODES * 256 * sizeof(float), 0);
        mma_gemm<<<dim3(4, MT), 256, GEMM_SMEM>>>(
            Y, 512, W1h + (long)i * 512 * 256, W1l + (long)i * 512 * 256, 256,
            nullptr, AB, nullptr, nullptr, 512, N_NODES, 256, 0, 0);
        cudaEventRecord(evG2, 0);

        // combine chunks on s2
        cudaStreamWaitEvent(s2, evG2, 0);
        for (int k = 0; k < NCH; k++) {
            cudaStreamWaitEvent(s2, evG3[k], 0);
            edge_combine_kernel<<<((long)ECH * 64) / 256, 256, 0, s2>>>(k * ECH);
        }
        cudaEventRecord(evComb, s2);
        cudaStreamWaitEvent(0, evComb, 0);

        // back on main stream
        cvt_kernel<<<((long)N_NODES * 256 + 255) / 256, 256>>>(P, Pf,
                                                               (long)N_NODES * 256);
        mma_gemm<<<dim3(2, MT), 256, GEMM_SMEM>>>(
            Pf, 256, W2h + (long)i * 256 * 256, W2l + (long)i * 256 * 256, 256,
            nullptr, G, nullptr, nullptr, 256, N_NODES, 256, 0, 0);
        ln_kernel<<<N_NODES, 256>>>(G, 256, mn_g + i * HDIM, mn_b + i * HDIM,
                                    eb2 + i * HDIM, deg, Y, 512, 256);
        mma_gemm<<<dim3(4, MT), 256, GEMM_SMEM>>>(
            Y, 512, N1h + (long)i * 512 * 512, N1l + (long)i * 512 * 512, 512,
            nb1 + i * 512, nullptr, T, nullptr, 512, N_NODES, 512, 1, 0);
        mma_gemm<<<dim3(2, MT), 256, GEMM_SMEM>>>(
            T, 512, N2h + (long)i * 256 * 512, N2l + (long)i * 256 * 512, 512,
            nb2 + i * HDIM, h, nullptr, hin, 256, N_NODES, 512, 0, 1);
    }
}

// round 10
// speedup vs baseline: 2.3736x; 1.2151x over previous
#include <cuda_runtime.h>
#include <cuda_fp16.h>
#include <math.h>
#include <stdint.h>

#define N_NODES 20000
#define NPAD    20096            // 157 * 128
#define N_EDGES 320000
#define ECH     80000            // edges per overlap chunk (4 chunks)
#define NCH     4
#define HDIM    256
#define S_STEPS 4

typedef __half h16;

// ---------------- device-global scratch (module-load allocated) -------------
__device__ h16   g_Y  [NPAD * 512];      // [hn | agg] fp16
__device__ float g_AB [NPAD * 512];      // [A | B] per node (fp32)
__device__ float g_C  [(size_t)N_EDGES * 256];  // ea@W1c + b1 per edge
__device__ float g_P  [NPAD * 256];      // segsum(silu(hidden))
__device__ h16   g_Pf [NPAD * 256];      // P as fp16
__device__ float g_G  [NPAD * 256];      // P @ eW2
__device__ h16   g_T  [NPAD * 512];      // silu(y@nW1+nb1) fp16
__device__ h16   g_ea [(size_t)N_EDGES * 64];
// transposed fp16 weights, per step ([N,K] row-major)
__device__ h16   g_W1 [4 * 512 * 256];
__device__ h16   g_Wc [4 * 256 * 64];
__device__ h16   g_W2 [4 * 256 * 256];
__device__ h16   g_N1 [4 * 512 * 512];
__device__ h16   g_N2 [4 * 256 * 512];
__device__ float g_deg[N_NODES];
__device__ int   g_src[N_EDGES];
__device__ int   g_dst[N_EDGES];
__device__ int   g_is64;

__device__ __forceinline__ float silu_f(float v) {
    return __fdividef(v, 1.0f + __expf(-v));
}

__device__ __forceinline__ uint32_t smem_u32(const void* p) {
    uint32_t a;
    asm("{ .reg .u64 t; cvta.to.shared.u64 t, %1; cvt.u32.u64 %0, t; }"
        : "=r"(a) : "l"(p));
    return a;
}

// ====================== small elementwise kernels ============================
__global__ void zero_detect(const long long* __restrict__ p) {
    int i = blockIdx.x * blockDim.x + threadIdx.x;
    if (i < N_NODES) g_deg[i] = 0.0f;
    if (blockIdx.x == 0) {
        __shared__ int bad;
        if (threadIdx.x == 0) bad = 0;
        __syncthreads();
        if (threadIdx.x < 64) {
            long long v = p[threadIdx.x];
            if (v < 0 || v >= N_NODES) bad = 1;
        }
        __syncthreads();
        if (threadIdx.x == 0) g_is64 = bad ? 0 : 1;
    }
}

__global__ void convert_idx_kernel(const void* __restrict__ ei) {
    int e = blockIdx.x * blockDim.x + threadIdx.x;
    if (e >= N_EDGES) return;
    int s, d;
    if (g_is64) {
        const long long* p = (const long long*)ei;
        s = (int)p[e]; d = (int)p[N_EDGES + e];
    } else {
        const int* p = (const int*)ei;
        s = p[e]; d = p[N_EDGES + e];
    }
    g_src[e] = s; g_dst[e] = d;
    atomicAdd(&g_deg[d], 1.0f);
}

// fp32 -> fp16 convert
__global__ void cvt_kernel(const float* __restrict__ in,
                           h16* __restrict__ out, long n) {
    long i = (long)blockIdx.x * blockDim.x + threadIdx.x;
    if (i >= n) return;
    out[i] = __float2half(in[i]);
}

// one launch transposes+converts ALL per-step weights (fp16).
__global__ void tsplit_all(const float* __restrict__ eW1,
                           const float* __restrict__ eW2,
                           const float* __restrict__ nW1,
                           const float* __restrict__ nW2) {
    const int z = blockIdx.z;
    const int step = z / 6, mat = z % 6;
    const float* W; int K, N; h16 *oh;
    switch (mat) {
    case 0: W = eW1 + (long)step * 576 * 256;             K = 256; N = 256;
            oh = g_W1 + (long)step * 512 * 256;            break;
    case 1: W = eW1 + (long)step * 576 * 256 + 256 * 256; K = 256; N = 256;
            oh = g_W1 + (long)step * 512 * 256 + 256*256;  break;
    case 2: W = eW1 + (long)step * 576 * 256 + 512 * 256; K = 64;  N = 256;
            oh = g_Wc + (long)step * 256 * 64;             break;
    case 3: W = eW2 + (long)step * 256 * 256;             K = 256; N = 256;
            oh = g_W2 + (long)step * 256 * 256;            break;
    case 4: W = nW1 + (long)step * 512 * 512;             K = 512; N = 512;
            oh = g_N1 + (long)step * 512 * 512;            break;
    default:W = nW2 + (long)step * 512 * 256;             K = 512; N = 256;
            oh = g_N2 + (long)step * 256 * 512;            break;
    }
    const int k0 = blockIdx.y * 32, n0 = blockIdx.x * 32;
    if (k0 >= K || n0 >= N) return;
    __shared__ float tile[32][33];
    const int tx = threadIdx.x, ty = threadIdx.y;   // 32 x 8
    #pragma unroll
    for (int i = 0; i < 32; i += 8) {
        int k = k0 + ty + i, n = n0 + tx;
        tile[ty + i][tx] = (k < K && n < N) ? W[(long)k * N + n] : 0.0f;
    }
    __syncthreads();
    #pragma unroll
    for (int i = 0; i < 32; i += 8) {
        int n = n0 + ty + i, k = k0 + tx;
        if (n < N && k < K)
            oh[(long)n * K + k] = __float2half(tile[tx][ty + i]);
    }
}

// ---------------- layer norm -> fp16 output ----------------------------------
__global__ void ln_kernel(const float* __restrict__ x, long ldx,
                          const float* __restrict__ gamma,
                          const float* __restrict__ beta,
                          const float* __restrict__ preBias,
                          const float* __restrict__ deg,
                          h16* __restrict__ out, long ldo, int colOff) {
    int n = blockIdx.x, t = threadIdx.x;
    float v = x[(long)n * ldx + t];
    if (deg) v = v / fmaxf(deg[n], 1.0f) + preBias[t];
    float s = v, s2 = v * v;
    #pragma unroll
    for (int o = 16; o; o >>= 1) {
        s  += __shfl_xor_sync(0xFFFFFFFFu, s,  o);
        s2 += __shfl_xor_sync(0xFFFFFFFFu, s2, o);
    }
    __shared__ float as[8], as2[8];
    int w = t >> 5, l = t & 31;
    if (l == 0) { as[w] = s; as2[w] = s2; }
    __syncthreads();
    float S = 0.f, S2 = 0.f;
    #pragma unroll
    for (int i = 0; i < 8; i++) { S += as[i]; S2 += as2[i]; }
    float mean = S * (1.0f / 256.0f);
    float var  = S2 * (1.0f / 256.0f) - mean * mean;
    float rstd = rsqrtf(var + 1e-5f);
    float r = (v - mean) * rstd * gamma[t] + beta[t];
    out[(long)n * ldo + colOff + t] = __float2half(r);
}

// ============== HMMA fp16 GEMM: Out = op(A@W^T + bias) =======================
// BM=128, BN=128, BK=32, 256 threads (8 warps = 2Mx4N, warp tile 64x32).
// Single fp16 term.  K % 32 == 0.  2 CTAs/SM.
#define PITCH 80
#define S_A  0
#define S_B  10240
#define STAGE 20480
#define GEMM_SMEM (2 * STAGE)

#define LDSM4(R, ADDR) \
    asm volatile("ldmatrix.sync.aligned.m8n8.x4.shared.b16 {%0,%1,%2,%3}, [%4];" \
                 : "=r"((R)[0]), "=r"((R)[1]), "=r"((R)[2]), "=r"((R)[3]) : "r"(ADDR))

#define MMA16816(C, A, B0, B1) \
    asm volatile("mma.sync.aligned.m16n8k16.row.col.f32.f16.f16.f32 " \
                 "{%0,%1,%2,%3}, {%4,%5,%6,%7}, {%8,%9}, {%0,%1,%2,%3};" \
                 : "+f"((C)[0]), "+f"((C)[1]), "+f"((C)[2]), "+f"((C)[3]) \
                 : "r"((A)[0]), "r"((A)[1]), "r"((A)[2]), "r"((A)[3]), \
                   "r"(B0), "r"(B1))

#define CP16(DST, SRC) \
    asm volatile("cp.async.cg.shared.global [%0], [%1], 16;" :: "r"(DST), "l"(SRC))

__global__ void __launch_bounds__(256, 2)
mma_gemm(const h16* __restrict__ A, long lda,
         const h16* __restrict__ B, long ldb,
         const float* __restrict__ bias,
         float* __restrict__ Out, h16* __restrict__ OutF,
         const float* __restrict__ AccIn,
         long ldo, int M, int K, int act, int accum) {
    extern __shared__ char smem[];
    const uint32_t sb = smem_u32(smem);
    const int tid  = threadIdx.x;
    const int lane = tid & 31;
    const int wid  = tid >> 5;
    const long bm = (long)blockIdx.y * 128;
    const long bn = (long)blockIdx.x * 128;
    const int wm = (wid & 1) * 64;
    const int wn = (wid >> 1) * 32;

    float acc[4][4][4];
    #pragma unroll
    for (int i = 0; i < 4; i++)
        #pragma unroll
        for (int j = 0; j < 4; j++)
            #pragma unroll
            for (int q = 0; q < 4; q++) acc[i][j][q] = 0.0f;

    const int nk = K >> 5;
    const int lrow0 = tid >> 2;          // 0..63 (+64 for odd sub-iter)
    const int lkc   = tid & 3;           // 16B chunk within 32-fp16 row

    #define ISSUE(kt) do {                                                     \
        const uint32_t st = sb + ((kt) & 1) * STAGE;                           \
        const long k0 = (long)(kt) << 5;                                       \
        _Pragma("unroll")                                                      \
        for (int i = 0; i < 4; i++) {                                          \
            const int part = i >> 1;                                           \
            const int row = lrow0 + (i & 1) * 64;                              \
            const uint32_t d = st + part * 10240 + row * PITCH + lkc * 16;     \
            const h16* g = part == 0 ? A + (bm + row) * lda + k0 + lkc * 8     \
                                     : B + (bn + row) * ldb + k0 + lkc * 8;    \
            CP16(d, g);                                                        \
        }                                                                      \
        asm volatile("cp.async.commit_group;");                                \
    } while (0)

    ISSUE(0);

    const uint32_t a_off = (uint32_t)((wm + (lane & 15)) * PITCH + (lane >> 4) * 16);
    const uint32_t b_off = (uint32_t)((wn + (lane & 15)) * PITCH + (lane >> 4) * 16);

    for (int kt = 0; kt < nk; kt++) {
        if (kt + 1 < nk) {
            ISSUE(kt + 1);
            asm volatile("cp.async.wait_group 1;");
        } else {
            asm volatile("cp.async.wait_group 0;");
        }
        __syncthreads();
        const uint32_t st = sb + (kt & 1) * STAGE;
        #pragma unroll
        for (int h = 0; h < 2; h++) {
            uint32_t a[4][4];
            #pragma unroll
            for (int mi = 0; mi < 4; mi++)
                LDSM4(a[mi], st + S_A + a_off + mi * (16 * PITCH) + h * 32);
            uint32_t bq[2][4];
            #pragma unroll
            for (int jj = 0; jj < 2; jj++)
                LDSM4(bq[jj], st + S_B + b_off + jj * (16 * PITCH) + h * 32);
            #pragma unroll
            for (int mi = 0; mi < 4; mi++)
                #pragma unroll
                for (int j = 0; j < 4; j++) {
                    const int jj = j >> 1, jo = j & 1;
                    MMA16816(acc[mi][j], a[mi], bq[jj][jo], bq[jj][2 + jo]);
                }
        }
        __syncthreads();
    }

    // ---------------- epilogue ----------------
    const int r0 = lane >> 2;
    const int c0 = (lane & 3) * 2;
    float2 bv[4];
    if (bias) {
        #pragma unroll
        for (int j = 0; j < 4; j++)
            bv[j] = *(const float2*)&bias[bn + wn + j * 8 + c0];
    } else {
        #pragma unroll
        for (int j = 0; j < 4; j++) bv[j] = make_float2(0.f, 0.f);
    }
    #pragma unroll
    for (int mi = 0; mi < 4; mi++) {
        #pragma unroll
        for (int half = 0; half < 2; half++) {
            const long m = bm + wm + mi * 16 + r0 + half * 8;
            if (m >= M) continue;
            #pragma unroll
            for (int j = 0; j < 4; j++) {
                float x = acc[mi][j][half * 2 + 0] + bv[j].x;
                float y = acc[mi][j][half * 2 + 1] + bv[j].y;
                if (act) { x = silu_f(x); y = silu_f(y); }
                const long col = bn + wn + j * 8 + c0;
                if (OutF) {
                    uint32_t hw = ((uint32_t)__half_as_ushort(__float2half(y)) << 16) |
                                  __half_as_ushort(__float2half(x));
                    *(uint32_t*)(OutF + m * ldo + col) = hw;
                } else {
                    if (accum) {
                        float2 old = *(const float2*)(AccIn + m * ldo + col);
                        x += old.x; y += old.y;
                    }
                    *(float2*)(Out + m * ldo + col) = make_float2(x, y);
                }
            }
        }
    }
    #undef ISSUE
}

// ---------------- edge combine: silu(A[src]+B[dst]+C[e]) scatter into P -----
__global__ void edge_combine_kernel(int ebase) {
    long idx = (long)blockIdx.x * blockDim.x + threadIdx.x;  // ECH * 64 items
    int e = ebase + (int)(idx >> 6);
    int j = ((int)idx & 63) << 2;
    int s = g_src[e];
    int d = g_dst[e];
    float4 a = *(const float4*)&g_AB[(long)s * 512 + j];
    float4 b = *(const float4*)&g_AB[(long)d * 512 + 256 + j];
    float4 c = *(const float4*)&g_C[(long)e * 256 + j];
    float r0 = silu_f(a.x + b.x + c.x);
    float r1 = silu_f(a.y + b.y + c.y);
    float r2 = silu_f(a.z + b.z + c.z);
    float r3 = silu_f(a.w + b.w + c.w);
    float* p = &g_P[(long)d * 256 + j];
    asm volatile("red.global.add.v4.f32 [%0], {%1,%2,%3,%4};"
                 :: "l"(p), "f"(r0), "f"(r1), "f"(r2), "f"(r3) : "memory");
}

// ============================ launch =========================================
extern "C" void kernel_launch(void* const* d_in, const int* in_sizes, int n_in,
                              void* d_out, int out_size) {
    const float* node_state = (const float*)d_in[0];
    const float* edge_attr  = (const float*)d_in[1];
    const float* nn_g = (const float*)d_in[2];
    const float* nn_b = (const float*)d_in[3];
    const float* mn_g = (const float*)d_in[4];
    const float* mn_b = (const float*)d_in[5];
    const float* eW1  = (const float*)d_in[6];
    const float* eb1  = (const float*)d_in[7];
    const float* eW2  = (const float*)d_in[8];
    const float* eb2  = (const float*)d_in[9];
    const float* nW1  = (const float*)d_in[10];
    const float* nb1  = (const float*)d_in[11];
    const float* nW2  = (const float*)d_in[12];
    const float* nb2  = (const float*)d_in[13];
    const void*  eidx = d_in[14];
    float* h = (float*)d_out;

    static bool inited = false;
    static cudaStream_t s1, s2;
    static cudaEvent_t evFork, evG2, evComb, evG3[NCH];
    if (!inited) {
        cudaStreamCreateWithFlags(&s1, cudaStreamNonBlocking);
        cudaStreamCreateWithFlags(&s2, cudaStreamNonBlocking);
        cudaEventCreateWithFlags(&evFork, cudaEventDisableTiming);
        cudaEventCreateWithFlags(&evG2,   cudaEventDisableTiming);
        cudaEventCreateWithFlags(&evComb, cudaEventDisableTiming);
        for (int k = 0; k < NCH; k++)
            cudaEventCreateWithFlags(&evG3[k], cudaEventDisableTiming);
        cudaFuncSetAttribute(mma_gemm, cudaFuncAttributeMaxDynamicSharedMemorySize,
                             GEMM_SMEM);
        inited = true;
    }

    void *pY, *pAB, *pC, *pP, *pPf, *pG, *pT, *pEa,
         *pW1, *pWc, *pW2, *pN1, *pN2, *pdeg;
    cudaGetSymbolAddress(&pY, g_Y);     cudaGetSymbolAddress(&pAB, g_AB);
    cudaGetSymbolAddress(&pC, g_C);     cudaGetSymbolAddress(&pP, g_P);
    cudaGetSymbolAddress(&pPf, g_Pf);   cudaGetSymbolAddress(&pG, g_G);
    cudaGetSymbolAddress(&pT, g_T);     cudaGetSymbolAddress(&pEa, g_ea);
    cudaGetSymbolAddress(&pW1, g_W1);   cudaGetSymbolAddress(&pWc, g_Wc);
    cudaGetSymbolAddress(&pW2, g_W2);   cudaGetSymbolAddress(&pN1, g_N1);
    cudaGetSymbolAddress(&pN2, g_N2);   cudaGetSymbolAddress(&pdeg, g_deg);

    h16 *Y=(h16*)pY, *Pf=(h16*)pPf, *T=(h16*)pT, *Ea=(h16*)pEa,
        *W1=(h16*)pW1, *Wc=(h16*)pWc, *W2=(h16*)pW2, *N1=(h16*)pN1,
        *N2=(h16*)pN2;
    float *AB=(float*)pAB, *C=(float*)pC, *P=(float*)pP, *G=(float*)pG,
          *deg=(float*)pdeg;

    // ---- prep: 4 kernel launches ----
    zero_detect<<<(N_NODES + 255) / 256, 256>>>((const long long*)eidx);
    convert_idx_kernel<<<(N_EDGES + 255) / 256, 256>>>(eidx);
    cvt_kernel<<<((long)N_EDGES * 64 + 255) / 256, 256>>>(edge_attr, Ea,
                                                          (long)N_EDGES * 64);
    tsplit_all<<<dim3(16, 16, 24), dim3(32, 8)>>>(eW1, eW2, nW1, nW2);

    const int MT = NPAD / 128;     // 157 M-tiles (node GEMMs)
    const int CT = ECH / 128;      // 625 M-tiles per edge chunk

    for (int i = 0; i < S_STEPS; i++) {
        const float* hin = (i == 0) ? node_state : h;

        // fork edge GEMM chunks onto s1
        cudaEventRecord(evFork, 0);
        cudaStreamWaitEvent(s1, evFork, 0);
        for (int k = 0; k < NCH; k++) {
            const size_t cb = (size_t)k * ECH;
            mma_gemm<<<dim3(2, CT), 256, GEMM_SMEM, s1>>>(
                Ea + cb * 64, 64,
                Wc + (long)i * 256 * 64, 64,
                eb1 + i * HDIM, C + cb * 256, nullptr, nullptr, 256,
                ECH, 64, 0, 0);
            cudaEventRecord(evG3[k], s1);
        }

        // main stream: ln -> memset P -> GEMM-2
        ln_kernel<<<N_NODES, 256>>>(hin, 256, nn_g + i * HDIM, nn_b + i * HDIM,
                                    nullptr, nullptr, Y, 512, 0);
        cudaMemsetAsync(pP, 0, (size_t)N_NODES * 256 * sizeof(float), 0);
        mma_gemm<<<dim3(4, MT), 256, GEMM_SMEM>>>(
            Y, 512, W1 + (long)i * 512 * 256, 256,
            nullptr, AB, nullptr, nullptr, 512, N_NODES, 256, 0, 0);
        cudaEventRecord(evG2, 0);

        // combine chunks on s2
        cudaStreamWaitEvent(s2, evG2, 0);
        for (int k = 0; k < NCH; k++) {
            cudaStreamWaitEvent(s2, evG3[k], 0);
            edge_combine_kernel<<<((long)ECH * 64) / 256, 256, 0, s2>>>(k * ECH);
        }
        cudaEventRecord(evComb, s2);
        cudaStreamWaitEvent(0, evComb, 0);

        // back on main stream
        cvt_kernel<<<((long)N_NODES * 256 + 255) / 256, 256>>>(P, Pf,
                                                               (long)N_NODES * 256);
        mma_gemm<<<dim3(2, MT), 256, GEMM_SMEM>>>(
            Pf, 256, W2 + (long)i * 256 * 256, 256,
            nullptr, G, nullptr, nullptr, 256, N_NODES, 256, 0, 0);
        ln_kernel<<<N_NODES, 256>>>(G, 256, mn_g + i * HDIM, mn_b + i * HDIM,
                                    eb2 + i * HDIM, deg, Y, 512, 256);
        mma_gemm<<<dim3(4, MT), 256, GEMM_SMEM>>>(
            Y, 512, N1 + (long)i * 512 * 512, 512,
            nb1 + i * 512, nullptr, T, nullptr, 512, N_NODES, 512, 1, 0);
        mma_gemm<<<dim3(2, MT), 256, GEMM_SMEM>>>(
            T, 512, N2 + (long)i * 256 * 512, 512,
            nb2 + i * HDIM, h, nullptr, hin, 256, N_NODES, 512, 0, 1);
    }
}

// round 11
// speedup vs baseline: 2.5240x; 1.0633x over previous
#include <cuda_runtime.h>
#include <cuda_fp16.h>
#include <math.h>
#include <stdint.h>

#define N_NODES 20000
#define NPAD    20096            // 157 * 128
#define N_EDGES 320000
#define ECH     80000            // edges per overlap chunk (4 chunks)
#define NCH     4
#define HDIM    256
#define S_STEPS 4

typedef __half h16;

// ---------------- device-global scratch (module-load allocated) -------------
__device__ h16   g_Y  [NPAD * 512];      // [hn | agg] fp16
__device__ h16   g_ABf[NPAD * 512];      // [A | B] per node (fp16)
__device__ h16   g_Cf [(size_t)N_EDGES * 256];  // ea@W1c + b1 per edge (fp16)
__device__ float g_P  [NPAD * 256];      // segsum(silu(hidden))
__device__ h16   g_Pf [NPAD * 256];      // P as fp16
__device__ float g_G  [NPAD * 256];      // P @ eW2
__device__ h16   g_T  [NPAD * 512];      // silu(y@nW1+nb1) fp16
__device__ h16   g_ea [(size_t)N_EDGES * 64];
// transposed fp16 weights, per step ([N,K] row-major)
__device__ h16   g_W1 [4 * 512 * 256];
__device__ h16   g_Wc [4 * 256 * 64];
__device__ h16   g_W2 [4 * 256 * 256];
__device__ h16   g_N1 [4 * 512 * 512];
__device__ h16   g_N2 [4 * 256 * 512];
__device__ float g_deg[N_NODES];
__device__ int   g_src[N_EDGES];
__device__ int   g_dst[N_EDGES];
__device__ int   g_is64;

__device__ __forceinline__ float silu_f(float v) {
    return __fdividef(v, 1.0f + __expf(-v));
}

__device__ __forceinline__ uint32_t smem_u32(const void* p) {
    uint32_t a;
    asm("{ .reg .u64 t; cvta.to.shared.u64 t, %1; cvt.u32.u64 %0, t; }"
        : "=r"(a) : "l"(p));
    return a;
}

// ====================== small elementwise kernels ============================
__global__ void zero_detect(const long long* __restrict__ p) {
    int i = blockIdx.x * blockDim.x + threadIdx.x;
    if (i < N_NODES) g_deg[i] = 0.0f;
    if (blockIdx.x == 0) {
        __shared__ int bad;
        if (threadIdx.x == 0) bad = 0;
        __syncthreads();
        if (threadIdx.x < 64) {
            long long v = p[threadIdx.x];
            if (v < 0 || v >= N_NODES) bad = 1;
        }
        __syncthreads();
        if (threadIdx.x == 0) g_is64 = bad ? 0 : 1;
    }
}

__global__ void convert_idx_kernel(const void* __restrict__ ei) {
    int e = blockIdx.x * blockDim.x + threadIdx.x;
    if (e >= N_EDGES) return;
    int s, d;
    if (g_is64) {
        const long long* p = (const long long*)ei;
        s = (int)p[e]; d = (int)p[N_EDGES + e];
    } else {
        const int* p = (const int*)ei;
        s = p[e]; d = p[N_EDGES + e];
    }
    g_src[e] = s; g_dst[e] = d;
    atomicAdd(&g_deg[d], 1.0f);
}

// fp32 -> fp16 convert
__global__ void cvt_kernel(const float* __restrict__ in,
                           h16* __restrict__ out, long n) {
    long i = (long)blockIdx.x * blockDim.x + threadIdx.x;
    if (i >= n) return;
    out[i] = __float2half(in[i]);
}

// one launch transposes+converts ALL per-step weights (fp16).
__global__ void tsplit_all(const float* __restrict__ eW1,
                           const float* __restrict__ eW2,
                           const float* __restrict__ nW1,
                           const float* __restrict__ nW2) {
    const int z = blockIdx.z;
    const int step = z / 6, mat = z % 6;
    const float* W; int K, N; h16 *oh;
    switch (mat) {
    case 0: W = eW1 + (long)step * 576 * 256;             K = 256; N = 256;
            oh = g_W1 + (long)step * 512 * 256;            break;
    case 1: W = eW1 + (long)step * 576 * 256 + 256 * 256; K = 256; N = 256;
            oh = g_W1 + (long)step * 512 * 256 + 256*256;  break;
    case 2: W = eW1 + (long)step * 576 * 256 + 512 * 256; K = 64;  N = 256;
            oh = g_Wc + (long)step * 256 * 64;             break;
    case 3: W = eW2 + (long)step * 256 * 256;             K = 256; N = 256;
            oh = g_W2 + (long)step * 256 * 256;            break;
    case 4: W = nW1 + (long)step * 512 * 512;             K = 512; N = 512;
            oh = g_N1 + (long)step * 512 * 512;            break;
    default:W = nW2 + (long)step * 512 * 256;             K = 512; N = 256;
            oh = g_N2 + (long)step * 256 * 512;            break;
    }
    const int k0 = blockIdx.y * 32, n0 = blockIdx.x * 32;
    if (k0 >= K || n0 >= N) return;
    __shared__ float tile[32][33];
    const int tx = threadIdx.x, ty = threadIdx.y;   // 32 x 8
    #pragma unroll
    for (int i = 0; i < 32; i += 8) {
        int k = k0 + ty + i, n = n0 + tx;
        tile[ty + i][tx] = (k < K && n < N) ? W[(long)k * N + n] : 0.0f;
    }
    __syncthreads();
    #pragma unroll
    for (int i = 0; i < 32; i += 8) {
        int n = n0 + ty + i, k = k0 + tx;
        if (n < N && k < K)
            oh[(long)n * K + k] = __float2half(tile[tx][ty + i]);
    }
}

// ---------------- layer norm -> fp16 output ----------------------------------
__global__ void ln_kernel(const float* __restrict__ x, long ldx,
                          const float* __restrict__ gamma,
                          const float* __restrict__ beta,
                          const float* __restrict__ preBias,
                          const float* __restrict__ deg,
                          h16* __restrict__ out, long ldo, int colOff) {
    int n = blockIdx.x, t = threadIdx.x;
    float v = x[(long)n * ldx + t];
    if (deg) v = v / fmaxf(deg[n], 1.0f) + preBias[t];
    float s = v, s2 = v * v;
    #pragma unroll
    for (int o = 16; o; o >>= 1) {
        s  += __shfl_xor_sync(0xFFFFFFFFu, s,  o);
        s2 += __shfl_xor_sync(0xFFFFFFFFu, s2, o);
    }
    __shared__ float as[8], as2[8];
    int w = t >> 5, l = t & 31;
    if (l == 0) { as[w] = s; as2[w] = s2; }
    __syncthreads();
    float S = 0.f, S2 = 0.f;
    #pragma unroll
    for (int i = 0; i < 8; i++) { S += as[i]; S2 += as2[i]; }
    float mean = S * (1.0f / 256.0f);
    float var  = S2 * (1.0f / 256.0f) - mean * mean;
    float rstd = rsqrtf(var + 1e-5f);
    float r = (v - mean) * rstd * gamma[t] + beta[t];
    out[(long)n * ldo + colOff + t] = __float2half(r);
}

// ============== HMMA fp16 GEMM: Out = op(A@W^T + bias) =======================
// BM=128, BN=128, BK=32, 256 threads (8 warps = 2Mx4N, warp tile 64x32).
// Single fp16 term.  K % 32 == 0.  2 CTAs/SM.
#define PITCH 80
#define S_A  0
#define S_B  10240
#define STAGE 20480
#define GEMM_SMEM (2 * STAGE)

#define LDSM4(R, ADDR) \
    asm volatile("ldmatrix.sync.aligned.m8n8.x4.shared.b16 {%0,%1,%2,%3}, [%4];" \
                 : "=r"((R)[0]), "=r"((R)[1]), "=r"((R)[2]), "=r"((R)[3]) : "r"(ADDR))

#define MMA16816(C, A, B0, B1) \
    asm volatile("mma.sync.aligned.m16n8k16.row.col.f32.f16.f16.f32 " \
                 "{%0,%1,%2,%3}, {%4,%5,%6,%7}, {%8,%9}, {%0,%1,%2,%3};" \
                 : "+f"((C)[0]), "+f"((C)[1]), "+f"((C)[2]), "+f"((C)[3]) \
                 : "r"((A)[0]), "r"((A)[1]), "r"((A)[2]), "r"((A)[3]), \
                   "r"(B0), "r"(B1))

#define CP16(DST, SRC) \
    asm volatile("cp.async.cg.shared.global [%0], [%1], 16;" :: "r"(DST), "l"(SRC))

__global__ void __launch_bounds__(256, 2)
mma_gemm(const h16* __restrict__ A, long lda,
         const h16* __restrict__ B, long ldb,
         const float* __restrict__ bias,
         float* __restrict__ Out, h16* __restrict__ OutF,
         const float* __restrict__ AccIn,
         long ldo, int M, int K, int act, int accum) {
    extern __shared__ char smem[];
    const uint32_t sb = smem_u32(smem);
    const int tid  = threadIdx.x;
    const int lane = tid & 31;
    const int wid  = tid >> 5;
    const long bm = (long)blockIdx.y * 128;
    const long bn = (long)blockIdx.x * 128;
    const int wm = (wid & 1) * 64;
    const int wn = (wid >> 1) * 32;

    float acc[4][4][4];
    #pragma unroll
    for (int i = 0; i < 4; i++)
        #pragma unroll
        for (int j = 0; j < 4; j++)
            #pragma unroll
            for (int q = 0; q < 4; q++) acc[i][j][q] = 0.0f;

    const int nk = K >> 5;
    const int lrow0 = tid >> 2;          // 0..63 (+64 for odd sub-iter)
    const int lkc   = tid & 3;           // 16B chunk within 32-fp16 row

    #define ISSUE(kt) do {                                                     \
        const uint32_t st = sb + ((kt) & 1) * STAGE;                           \
        const long k0 = (long)(kt) << 5;                                       \
        _Pragma("unroll")                                                      \
        for (int i = 0; i < 4; i++) {                                          \
            const int part = i >> 1;                                           \
            const int row = lrow0 + (i & 1) * 64;                              \
            const uint32_t d = st + part * 10240 + row * PITCH + lkc * 16;     \
            const h16* g = part == 0 ? A + (bm + row) * lda + k0 + lkc * 8     \
                                     : B + (bn + row) * ldb + k0 + lkc * 8;    \
            CP16(d, g);                                                        \
        }                                                                      \
        asm volatile("cp.async.commit_group;");                                \
    } while (0)

    ISSUE(0);

    const uint32_t a_off = (uint32_t)((wm + (lane & 15)) * PITCH + (lane >> 4) * 16);
    const uint32_t b_off = (uint32_t)((wn + (lane & 15)) * PITCH + (lane >> 4) * 16);

    for (int kt = 0; kt < nk; kt++) {
        if (kt + 1 < nk) {
            ISSUE(kt + 1);
            asm volatile("cp.async.wait_group 1;");
        } else {
            asm volatile("cp.async.wait_group 0;");
        }
        __syncthreads();
        const uint32_t st = sb + (kt & 1) * STAGE;
        #pragma unroll
        for (int h = 0; h < 2; h++) {
            uint32_t a[4][4];
            #pragma unroll
            for (int mi = 0; mi < 4; mi++)
                LDSM4(a[mi], st + S_A + a_off + mi * (16 * PITCH) + h * 32);
            uint32_t bq[2][4];
            #pragma unroll
            for (int jj = 0; jj < 2; jj++)
                LDSM4(bq[jj], st + S_B + b_off + jj * (16 * PITCH) + h * 32);
            #pragma unroll
            for (int mi = 0; mi < 4; mi++)
                #pragma unroll
                for (int j = 0; j < 4; j++) {
                    const int jj = j >> 1, jo = j & 1;
                    MMA16816(acc[mi][j], a[mi], bq[jj][jo], bq[jj][2 + jo]);
                }
        }
        __syncthreads();
    }

    // ---------------- epilogue ----------------
    const int r0 = lane >> 2;
    const int c0 = (lane & 3) * 2;
    float2 bv[4];
    if (bias) {
        #pragma unroll
        for (int j = 0; j < 4; j++)
            bv[j] = *(const float2*)&bias[bn + wn + j * 8 + c0];
    } else {
        #pragma unroll
        for (int j = 0; j < 4; j++) bv[j] = make_float2(0.f, 0.f);
    }
    #pragma unroll
    for (int mi = 0; mi < 4; mi++) {
        #pragma unroll
        for (int half = 0; half < 2; half++) {
            const long m = bm + wm + mi * 16 + r0 + half * 8;
            if (m >= M) continue;
            #pragma unroll
            for (int j = 0; j < 4; j++) {
                float x = acc[mi][j][half * 2 + 0] + bv[j].x;
                float y = acc[mi][j][half * 2 + 1] + bv[j].y;
                if (act) { x = silu_f(x); y = silu_f(y); }
                const long col = bn + wn + j * 8 + c0;
                if (OutF) {
                    uint32_t hw = ((uint32_t)__half_as_ushort(__float2half(y)) << 16) |
                                  __half_as_ushort(__float2half(x));
                    *(uint32_t*)(OutF + m * ldo + col) = hw;
                } else {
                    if (accum) {
                        float2 old = *(const float2*)(AccIn + m * ldo + col);
                        x += old.x; y += old.y;
                    }
                    *(float2*)(Out + m * ldo + col) = make_float2(x, y);
                }
            }
        }
    }
    #undef ISSUE
}

// ---------------- edge combine: silu(A[src]+B[dst]+C[e]) scatter into P -----
// fp16 inputs: each thread handles 8 columns (one uint4 of halves).
__global__ void edge_combine_kernel(int ebase) {
    long idx = (long)blockIdx.x * blockDim.x + threadIdx.x;  // ECH * 32 items
    int e = ebase + (int)(idx >> 5);
    int j = ((int)idx & 31) << 3;     // column offset (8 halves)
    int s = g_src[e];
    int d = g_dst[e];
    const uint4 ua = *(const uint4*)&g_ABf[(long)s * 512 + j];
    const uint4 ub = *(const uint4*)&g_ABf[(long)d * 512 + 256 + j];
    const uint4 uc = *(const uint4*)&g_Cf[(long)e * 256 + j];
    const uint32_t* pa = &ua.x;
    const uint32_t* pb = &ub.x;
    const uint32_t* pc = &uc.x;
    float v[8];
    #pragma unroll
    for (int q = 0; q < 4; q++) {
        float2 fa = __half22float2(*(const __half2*)&pa[q]);
        float2 fb = __half22float2(*(const __half2*)&pb[q]);
        float2 fc = __half22float2(*(const __half2*)&pc[q]);
        v[2 * q + 0] = silu_f(fa.x + fb.x + fc.x);
        v[2 * q + 1] = silu_f(fa.y + fb.y + fc.y);
    }
    float* p = &g_P[(long)d * 256 + j];
    asm volatile("red.global.add.v4.f32 [%0], {%1,%2,%3,%4};"
                 :: "l"(p), "f"(v[0]), "f"(v[1]), "f"(v[2]), "f"(v[3]) : "memory");
    asm volatile("red.global.add.v4.f32 [%0], {%1,%2,%3,%4};"
                 :: "l"(p + 4), "f"(v[4]), "f"(v[5]), "f"(v[6]), "f"(v[7]) : "memory");
}

// ============================ launch =========================================
extern "C" void kernel_launch(void* const* d_in, const int* in_sizes, int n_in,
                              void* d_out, int out_size) {
    const float* node_state = (const float*)d_in[0];
    const float* edge_attr  = (const float*)d_in[1];
    const float* nn_g = (const float*)d_in[2];
    const float* nn_b = (const float*)d_in[3];
    const float* mn_g = (const float*)d_in[4];
    const float* mn_b = (const float*)d_in[5];
    const float* eW1  = (const float*)d_in[6];
    const float* eb1  = (const float*)d_in[7];
    const float* eW2  = (const float*)d_in[8];
    const float* eb2  = (const float*)d_in[9];
    const float* nW1  = (const float*)d_in[10];
    const float* nb1  = (const float*)d_in[11];
    const float* nW2  = (const float*)d_in[12];
    const float* nb2  = (const float*)d_in[13];
    const void*  eidx = d_in[14];
    float* h = (float*)d_out;

    static bool inited = false;
    static cudaStream_t s1, s2;
    static cudaEvent_t evFork, evG2, evComb, evG3[NCH];
    if (!inited) {
        cudaStreamCreateWithFlags(&s1, cudaStreamNonBlocking);
        cudaStreamCreateWithFlags(&s2, cudaStreamNonBlocking);
        cudaEventCreateWithFlags(&evFork, cudaEventDisableTiming);
        cudaEventCreateWithFlags(&evG2,   cudaEventDisableTiming);
        cudaEventCreateWithFlags(&evComb, cudaEventDisableTiming);
        for (int k = 0; k < NCH; k++)
            cudaEventCreateWithFlags(&evG3[k], cudaEventDisableTiming);
        cudaFuncSetAttribute(mma_gemm, cudaFuncAttributeMaxDynamicSharedMemorySize,
                             GEMM_SMEM);
        inited = true;
    }

    void *pY, *pABf, *pCf, *pP, *pPf, *pG, *pT, *pEa,
         *pW1, *pWc, *pW2, *pN1, *pN2, *pdeg;
    cudaGetSymbolAddress(&pY, g_Y);     cudaGetSymbolAddress(&pABf, g_ABf);
    cudaGetSymbolAddress(&pCf, g_Cf);   cudaGetSymbolAddress(&pP, g_P);
    cudaGetSymbolAddress(&pPf, g_Pf);   cudaGetSymbolAddress(&pG, g_G);
    cudaGetSymbolAddress(&pT, g_T);     cudaGetSymbolAddress(&pEa, g_ea);
    cudaGetSymbolAddress(&pW1, g_W1);   cudaGetSymbolAddress(&pWc, g_Wc);
    cudaGetSymbolAddress(&pW2, g_W2);   cudaGetSymbolAddress(&pN1, g_N1);
    cudaGetSymbolAddress(&pN2, g_N2);   cudaGetSymbolAddress(&pdeg, g_deg);

    h16 *Y=(h16*)pY, *ABf=(h16*)pABf, *Cf=(h16*)pCf, *Pf=(h16*)pPf,
        *T=(h16*)pT, *Ea=(h16*)pEa,
        *W1=(h16*)pW1, *Wc=(h16*)pWc, *W2=(h16*)pW2, *N1=(h16*)pN1,
        *N2=(h16*)pN2;
    float *P=(float*)pP, *G=(float*)pG, *deg=(float*)pdeg;

    // ---- prep: 4 kernel launches ----
    zero_detect<<<(N_NODES + 255) / 256, 256>>>((const long long*)eidx);
    convert_idx_kernel<<<(N_EDGES + 255) / 256, 256>>>(eidx);
    cvt_kernel<<<((long)N_EDGES * 64 + 255) / 256, 256>>>(edge_attr, Ea,
                                                          (long)N_EDGES * 64);
    tsplit_all<<<dim3(16, 16, 24), dim3(32, 8)>>>(eW1, eW2, nW1, nW2);

    const int MT = NPAD / 128;     // 157 M-tiles (node GEMMs)
    const int CT = ECH / 128;      // 625 M-tiles per edge chunk

    for (int i = 0; i < S_STEPS; i++) {
        const float* hin = (i == 0) ? node_state : h;

        // fork edge GEMM chunks onto s1  (fp16 C output)
        cudaEventRecord(evFork, 0);
        cudaStreamWaitEvent(s1, evFork, 0);
        for (int k = 0; k < NCH; k++) {
            const size_t cb = (size_t)k * ECH;
            mma_gemm<<<dim3(2, CT), 256, GEMM_SMEM, s1>>>(
                Ea + cb * 64, 64,
                Wc + (long)i * 256 * 64, 64,
                eb1 + i * HDIM, nullptr, Cf + cb * 256, nullptr, 256,
                ECH, 64, 0, 0);
            cudaEventRecord(evG3[k], s1);
        }

        // main stream: ln -> memset P -> GEMM-2 (fp16 AB output)
        ln_kernel<<<N_NODES, 256>>>(hin, 256, nn_g + i * HDIM, nn_b + i * HDIM,
                                    nullptr, nullptr, Y, 512, 0);
        cudaMemsetAsync(pP, 0, (size_t)N_NODES * 256 * sizeof(float), 0);
        mma_gemm<<<dim3(4, MT), 256, GEMM_SMEM>>>(
            Y, 512, W1 + (long)i * 512 * 256, 256,
            nullptr, nullptr, ABf, nullptr, 512, N_NODES, 256, 0, 0);
        cudaEventRecord(evG2, 0);

        // combine chunks on s2
        cudaStreamWaitEvent(s2, evG2, 0);
        for (int k = 0; k < NCH; k++) {
            cudaStreamWaitEvent(s2, evG3[k], 0);
            edge_combine_kernel<<<((long)ECH * 32) / 256, 256, 0, s2>>>(k * ECH);
        }
        cudaEventRecord(evComb, s2);
        cudaStreamWaitEvent(0, evComb, 0);

        // back on main stream
        cvt_kernel<<<((long)N_NODES * 256 + 255) / 256, 256>>>(P, Pf,
                                                               (long)N_NODES * 256);
        mma_gemm<<<dim3(2, MT), 256, GEMM_SMEM>>>(
            Pf, 256, W2 + (long)i * 256 * 256, 256,
            nullptr, G, nullptr, nullptr, 256, N_NODES, 256, 0, 0);
        ln_kernel<<<N_NODES, 256>>>(G, 256, mn_g + i * HDIM, mn_b + i * HDIM,
                                    eb2 + i * HDIM, deg, Y, 512, 256);
        mma_gemm<<<dim3(4, MT), 256, GEMM_SMEM>>>(
            Y, 512, N1 + (long)i * 512 * 512, 512,
            nb1 + i * 512, nullptr, T, nullptr, 512, N_NODES, 512, 1, 0);
        mma_gemm<<<dim3(2, MT), 256, GEMM_SMEM>>>(
            T, 512, N2 + (long)i * 256 * 512, 512,
            nb2 + i * HDIM, h, nullptr, hin, 256, N_NODES, 512, 0, 1);
    }
}